// round 2
// baseline (speedup 1.0000x reference)
#include <cuda_runtime.h>
#include <math.h>

// Problem constants
#define BB 2
#define LL 2048
#define DD 1024
#define HH 16
#define DH 64

// Scratch (device globals; no allocation allowed)
__device__ float g_q[BB * LL * DD];
__device__ float g_k[BB * LL * DD];
__device__ float g_v[BB * LL * DD];
__device__ float g_o[BB * LL * DD];

// ---------------------------------------------------------------------------
// SGEMM: C[M,N] = A[M,K] @ B[K,N], all row-major. M%128==0, N%128==0, K%8==0.
// 128x128 block tile, BK=8, 256 threads, 8x8 per thread.
// ---------------------------------------------------------------------------
__global__ __launch_bounds__(256) void sgemm_kernel(
    const float* __restrict__ A, const float* __restrict__ B,
    float* __restrict__ C, int M, int N, int K)
{
    __shared__ float As[8][128];   // transposed A tile
    __shared__ float Bs[8][128];

    const int tid = threadIdx.x;
    const int cRow = blockIdx.y;   // M tile
    const int cCol = blockIdx.x;   // N tile

    const int threadRow = tid / 16;        // 0..15
    const int threadCol = tid % 16;        // 0..15

    const int innerRowA = tid / 2;         // 0..127
    const int innerColA = (tid % 2) * 4;   // 0 or 4
    const int innerRowB = tid / 32;        // 0..7
    const int innerColB = (tid % 32) * 4;  // 0..124

    const float* Ab = A + (size_t)cRow * 128 * K;
    const float* Bb = B + cCol * 128;

    float acc[8][8];
#pragma unroll
    for (int i = 0; i < 8; i++)
#pragma unroll
        for (int j = 0; j < 8; j++) acc[i][j] = 0.0f;

    for (int k0 = 0; k0 < K; k0 += 8) {
        float4 a4 = *reinterpret_cast<const float4*>(Ab + (size_t)innerRowA * K + k0 + innerColA);
        As[innerColA + 0][innerRowA] = a4.x;
        As[innerColA + 1][innerRowA] = a4.y;
        As[innerColA + 2][innerRowA] = a4.z;
        As[innerColA + 3][innerRowA] = a4.w;
        float4 b4 = *reinterpret_cast<const float4*>(Bb + (size_t)(k0 + innerRowB) * N + innerColB);
        *reinterpret_cast<float4*>(&Bs[innerRowB][innerColB]) = b4;
        __syncthreads();

#pragma unroll
        for (int d = 0; d < 8; d++) {
            float4 m0 = *reinterpret_cast<float4*>(&As[d][threadRow * 8]);
            float4 m1 = *reinterpret_cast<float4*>(&As[d][threadRow * 8 + 4]);
            float4 n0 = *reinterpret_cast<float4*>(&Bs[d][threadCol * 8]);
            float4 n1 = *reinterpret_cast<float4*>(&Bs[d][threadCol * 8 + 4]);
            float regM[8] = {m0.x, m0.y, m0.z, m0.w, m1.x, m1.y, m1.z, m1.w};
            float regN[8] = {n0.x, n0.y, n0.z, n0.w, n1.x, n1.y, n1.z, n1.w};
#pragma unroll
            for (int i = 0; i < 8; i++)
#pragma unroll
                for (int j = 0; j < 8; j++)
                    acc[i][j] += regM[i] * regN[j];
        }
        __syncthreads();
    }

#pragma unroll
    for (int i = 0; i < 8; i++) {
        int row = cRow * 128 + threadRow * 8 + i;
        float* Cp = C + (size_t)row * N + cCol * 128 + threadCol * 8;
        *reinterpret_cast<float4*>(Cp)     = make_float4(acc[i][0], acc[i][1], acc[i][2], acc[i][3]);
        *reinterpret_cast<float4*>(Cp + 4) = make_float4(acc[i][4], acc[i][5], acc[i][6], acc[i][7]);
    }
}

// ---------------------------------------------------------------------------
// Flash attention, fp32, causal. One block per (q-tile of 64, head, batch).
// 256 threads: ty = tid/16 (row group of 4), tx = tid%16 (col groups).
// Q/K/V/O layout: [B, L, H, DH] -> elem (b,l,h,d) at (b*L + l)*1024 + h*64 + d.
// ---------------------------------------------------------------------------
#define KPAD 68   // 16B-aligned row stride for K/V/Q tiles
__global__ __launch_bounds__(256) void attn_kernel(
    const float* __restrict__ Q, const float* __restrict__ K,
    const float* __restrict__ V, float* __restrict__ O)
{
    __shared__ float Qs[64][KPAD];
    __shared__ float Ks[32][KPAD];
    __shared__ float Vs[32][KPAD];
    __shared__ float Ps[64][33];

    const int tid = threadIdx.x;
    const int ty = tid / 16;   // 0..15 -> owns rows ty*4 .. ty*4+3
    const int tx = tid % 16;   // score cols tx*2, tx*2+1 ; O cols tx*4..tx*4+3

    const int b  = blockIdx.z;
    const int h  = blockIdx.y;
    const int qt = blockIdx.x;
    const int qb = qt * 64;

    const size_t base = (size_t)b * LL * DD + (size_t)h * DH;
    const float* Qb = Q + base;
    const float* Kb = K + base;
    const float* Vb = V + base;
    float* Ob = O + base;

    // Load Q tile
    for (int idx = tid; idx < 64 * 64; idx += 256) {
        int r = idx >> 6, d = idx & 63;
        Qs[r][d] = Qb[(size_t)(qb + r) * DD + d];
    }

    float m[4], l[4], acc[4][4];
#pragma unroll
    for (int i = 0; i < 4; i++) {
        m[i] = -1e30f;
        l[i] = 0.0f;
#pragma unroll
        for (int c = 0; c < 4; c++) acc[i][c] = 0.0f;
    }
    __syncthreads();

    const int ktiles = 2 * qt + 2;   // tiles of 32 up to and including diagonal
    for (int kt = 0; kt < ktiles; kt++) {
        const int kb = kt * 32;
        // Load K,V tiles
        for (int idx = tid; idx < 32 * 64; idx += 256) {
            int r = idx >> 6, d = idx & 63;
            Ks[r][d] = Kb[(size_t)(kb + r) * DD + d];
            Vs[r][d] = Vb[(size_t)(kb + r) * DD + d];
        }
        __syncthreads();

        // S = (Q @ K^T) * 1/sqrt(64)
        float s0[4], s1[4];
#pragma unroll
        for (int i = 0; i < 4; i++) { s0[i] = 0.0f; s1[i] = 0.0f; }
        const int c0 = tx * 2, c1 = tx * 2 + 1;
#pragma unroll
        for (int d0 = 0; d0 < 64; d0 += 4) {
            float4 k0 = *reinterpret_cast<float4*>(&Ks[c0][d0]);
            float4 k1 = *reinterpret_cast<float4*>(&Ks[c1][d0]);
#pragma unroll
            for (int i = 0; i < 4; i++) {
                float4 qv = *reinterpret_cast<float4*>(&Qs[ty * 4 + i][d0]);
                s0[i] += qv.x * k0.x + qv.y * k0.y + qv.z * k0.z + qv.w * k0.w;
                s1[i] += qv.x * k1.x + qv.y * k1.y + qv.z * k1.z + qv.w * k1.w;
            }
        }

        // scale + causal mask
#pragma unroll
        for (int i = 0; i < 4; i++) {
            int gr = qb + ty * 4 + i;
            s0[i] = (kb + c0 <= gr) ? s0[i] * 0.125f : -1e30f;
            s1[i] = (kb + c1 <= gr) ? s1[i] * 0.125f : -1e30f;
        }

        // row max over the 16 tx lanes (lanes with same ty are 16 contiguous)
        float rmax[4];
#pragma unroll
        for (int i = 0; i < 4; i++) rmax[i] = fmaxf(s0[i], s1[i]);
#pragma unroll
        for (int off = 8; off >= 1; off >>= 1)
#pragma unroll
            for (int i = 0; i < 4; i++)
                rmax[i] = fmaxf(rmax[i], __shfl_xor_sync(0xffffffffu, rmax[i], off));

        float scale[4], rsum[4];
#pragma unroll
        for (int i = 0; i < 4; i++) {
            float mn = fmaxf(m[i], rmax[i]);
            scale[i] = __expf(m[i] - mn);
            m[i] = mn;
            s0[i] = __expf(s0[i] - mn);
            s1[i] = __expf(s1[i] - mn);
            rsum[i] = s0[i] + s1[i];
        }
#pragma unroll
        for (int off = 8; off >= 1; off >>= 1)
#pragma unroll
            for (int i = 0; i < 4; i++)
                rsum[i] += __shfl_xor_sync(0xffffffffu, rsum[i], off);

#pragma unroll
        for (int i = 0; i < 4; i++) {
            l[i] = l[i] * scale[i] + rsum[i];
            Ps[ty * 4 + i][c0] = s0[i];
            Ps[ty * 4 + i][c1] = s1[i];
#pragma unroll
            for (int c = 0; c < 4; c++) acc[i][c] *= scale[i];
        }
        __syncthreads();

        // O += P @ V   (O cols tx*4..tx*4+3)
#pragma unroll 4
        for (int k = 0; k < 32; k++) {
            float4 vv = *reinterpret_cast<float4*>(&Vs[k][tx * 4]);
#pragma unroll
            for (int i = 0; i < 4; i++) {
                float p = Ps[ty * 4 + i][k];
                acc[i][0] += p * vv.x;
                acc[i][1] += p * vv.y;
                acc[i][2] += p * vv.z;
                acc[i][3] += p * vv.w;
            }
        }
        __syncthreads();
    }

    // Epilogue: normalize and store
#pragma unroll
    for (int i = 0; i < 4; i++) {
        float inv = 1.0f / l[i];
        float* Op = Ob + (size_t)(qb + ty * 4 + i) * DD + tx * 4;
        *reinterpret_cast<float4*>(Op) =
            make_float4(acc[i][0] * inv, acc[i][1] * inv, acc[i][2] * inv, acc[i][3] * inv);
    }
}

// ---------------------------------------------------------------------------
extern "C" void kernel_launch(void* const* d_in, const int* in_sizes, int n_in,
                              void* d_out, int out_size)
{
    (void)in_sizes; (void)n_in; (void)out_size;
    const float* x    = (const float*)d_in[0];
    const float* Wq   = (const float*)d_in[1];
    const float* Wk   = (const float*)d_in[2];
    const float* Wv   = (const float*)d_in[3];
    const float* Wout = (const float*)d_in[4];
    float* out = (float*)d_out;

    float *q, *k, *v, *o;
    cudaGetSymbolAddress((void**)&q, g_q);
    cudaGetSymbolAddress((void**)&k, g_k);
    cudaGetSymbolAddress((void**)&v, g_v);
    cudaGetSymbolAddress((void**)&o, g_o);

    const int M = BB * LL;   // 4096
    const int N = DD;        // 1024
    const int Kd = DD;       // 1024
    dim3 gg(N / 128, M / 128);

    sgemm_kernel<<<gg, 256>>>(x, Wq, q, M, N, Kd);
    sgemm_kernel<<<gg, 256>>>(x, Wk, k, M, N, Kd);
    sgemm_kernel<<<gg, 256>>>(x, Wv, v, M, N, Kd);

    dim3 ga(LL / 64, HH, BB);
    attn_kernel<<<ga, 256>>>(q, k, v, o);

    sgemm_kernel<<<gg, 256>>>(o, Wout, out, M, N, Kd);
}

// round 6
// speedup vs baseline: 1.4642x; 1.4642x over previous
#include <cuda_runtime.h>
#include <math.h>
#include <stdint.h>

// Problem constants
#define BB 2
#define LL 2048
#define DD 1024
#define HH 16
#define DH 64

// Scratch (device globals; no allocation allowed)
__device__ float g_q[BB * LL * DD];
__device__ float g_k[BB * LL * DD];
__device__ float g_v[BB * LL * DD];
__device__ float g_o[BB * LL * DD];

// ---------------------------------------------------------------------------
// Helpers
// ---------------------------------------------------------------------------
__device__ __forceinline__ uint32_t s2u(const void* p) {
    return (uint32_t)__cvta_generic_to_shared(p);
}

__device__ __forceinline__ void mma_tf32(float* c, const uint32_t* a, const uint32_t* b) {
    asm volatile(
        "mma.sync.aligned.m16n8k8.row.col.f32.tf32.tf32.f32 "
        "{%0,%1,%2,%3}, {%4,%5,%6,%7}, {%8,%9}, {%0,%1,%2,%3};\n"
        : "+f"(c[0]), "+f"(c[1]), "+f"(c[2]), "+f"(c[3])
        : "r"(a[0]), "r"(a[1]), "r"(a[2]), "r"(a[3]), "r"(b[0]), "r"(b[1]));
}

__device__ __forceinline__ uint32_t f2tf(float x) {
    uint32_t r;
    asm("cvt.rna.tf32.f32 %0, %1;\n" : "=r"(r) : "f"(x));
    return r;
}
// split fp32 (bit pattern in u) into tf32 hi + tf32 lo
__device__ __forceinline__ void tfsplit(uint32_t u, uint32_t& hi, uint32_t& lo) {
    float x = __uint_as_float(u);
    hi = f2tf(x);
    lo = f2tf(x - __uint_as_float(hi));
}

// 3xTF32 compensated mma: c += a*b with ~22-bit mantissa accuracy
__device__ __forceinline__ void mma3(float* c, const uint32_t* ah, const uint32_t* al,
                                     const uint32_t* bh, const uint32_t* bl) {
    mma_tf32(c, al, bh);
    mma_tf32(c, ah, bl);
    mma_tf32(c, ah, bh);
}

__device__ __forceinline__ void cp_async16(uint32_t dst, const void* src) {
    asm volatile("cp.async.ca.shared.global [%0], [%1], 16;\n" :: "r"(dst), "l"(src));
}
__device__ __forceinline__ void cp_commit() {
    asm volatile("cp.async.commit_group;\n");
}
__device__ __forceinline__ void cp_wait0() {
    asm volatile("cp.async.wait_group 0;\n" ::: "memory");
}

// ---------------------------------------------------------------------------
// TF32x3 GEMM: C[M,N] = A[M,K] @ B[K,N], row-major. M%128==0, N%128==0, K%16==0.
// Block tile 128x128, BK=16, 256 threads = 8 warps (2m x 4n), warp tile 64x32.
// ---------------------------------------------------------------------------
#define ASTR 20
#define BSTR 136
__global__ __launch_bounds__(256) void gemm_tf32(
    const float* __restrict__ A, const float* __restrict__ B,
    float* __restrict__ C, int M, int N, int K)
{
    __shared__ float As[2][128 * ASTR];
    __shared__ float Bs[2][16 * BSTR];

    const int tid = threadIdx.x;
    const int lane = tid & 31;
    const int wid = tid >> 5;
    const int warp_m = wid & 1;   // 0..1
    const int warp_n = wid >> 1;  // 0..3
    const int lq = lane >> 2;     // 0..7
    const int lr = lane & 3;      // 0..3

    const int bm = blockIdx.y * 128;
    const int bn = blockIdx.x * 128;

    float acc[4][4][4];
#pragma unroll
    for (int mi = 0; mi < 4; mi++)
#pragma unroll
        for (int ni = 0; ni < 4; ni++)
#pragma unroll
            for (int q = 0; q < 4; q++) acc[mi][ni][q] = 0.0f;

    const uint32_t sA = s2u(&As[0][0]);
    const uint32_t sB = s2u(&Bs[0][0]);

    auto load_tiles = [&](int buf, int k0) {
#pragma unroll
        for (int i = 0; i < 2; i++) {
            int c = tid + i * 256;
            int r = c >> 2, kc = (c & 3) * 4;
            cp_async16(sA + (uint32_t)(buf * 128 * ASTR + r * ASTR + kc) * 4,
                       A + (size_t)(bm + r) * K + k0 + kc);
        }
#pragma unroll
        for (int i = 0; i < 2; i++) {
            int c = tid + i * 256;
            int r = c >> 5, nc = (c & 31) * 4;
            cp_async16(sB + (uint32_t)(buf * 16 * BSTR + r * BSTR + nc) * 4,
                       B + (size_t)(k0 + r) * N + bn + nc);
        }
        cp_commit();
    };

    load_tiles(0, 0);
    const int T = K / 16;

    for (int t = 0; t < T; t++) {
        cp_wait0();
        __syncthreads();
        if (t + 1 < T) load_tiles((t + 1) & 1, (t + 1) * 16);

        const uint32_t* Au = (const uint32_t*)&As[t & 1][0];
        const uint32_t* Bu = (const uint32_t*)&Bs[t & 1][0];

#pragma unroll
        for (int kk = 0; kk < 2; kk++) {
            const int kbase = kk * 8;
            uint32_t ah[4][4], al[4][4];
#pragma unroll
            for (int mi = 0; mi < 4; mi++) {
                int r = warp_m * 64 + mi * 16 + lq;
                int c = kbase + lr;
                tfsplit(Au[r * ASTR + c],           ah[mi][0], al[mi][0]);
                tfsplit(Au[(r + 8) * ASTR + c],     ah[mi][1], al[mi][1]);
                tfsplit(Au[r * ASTR + c + 4],       ah[mi][2], al[mi][2]);
                tfsplit(Au[(r + 8) * ASTR + c + 4], ah[mi][3], al[mi][3]);
            }
#pragma unroll
            for (int ni = 0; ni < 4; ni++) {
                uint32_t bh[2], bl[2];
                int cc = warp_n * 32 + ni * 8 + lq;
                tfsplit(Bu[(kbase + lr) * BSTR + cc],     bh[0], bl[0]);
                tfsplit(Bu[(kbase + lr + 4) * BSTR + cc], bh[1], bl[1]);
#pragma unroll
                for (int mi = 0; mi < 4; mi++)
                    mma3(acc[mi][ni], ah[mi], al[mi], bh, bl);
            }
        }
        __syncthreads();
    }

#pragma unroll
    for (int mi = 0; mi < 4; mi++) {
#pragma unroll
        for (int ni = 0; ni < 4; ni++) {
            int r = bm + warp_m * 64 + mi * 16 + lq;
            int cc = bn + warp_n * 32 + ni * 8 + lr * 2;
            *(float2*)&C[(size_t)r * N + cc] = make_float2(acc[mi][ni][0], acc[mi][ni][1]);
            *(float2*)&C[(size_t)(r + 8) * N + cc] = make_float2(acc[mi][ni][2], acc[mi][ni][3]);
        }
    }
}

// ---------------------------------------------------------------------------
// TF32x3 flash attention, causal. Block = 128 threads (4 warps), BQ=128, BKV=64.
// ---------------------------------------------------------------------------
#define QSTR 68
#define KSTR 72
__global__ __launch_bounds__(128) void attn_tf32(
    const float* __restrict__ Q, const float* __restrict__ K,
    const float* __restrict__ V, float* __restrict__ O)
{
    extern __shared__ float sm[];
    float* Qs = sm;                       // 128 * QSTR
    float* Ps = Qs + 128 * QSTR;          // 128 * QSTR
    float* Ks = Ps + 128 * QSTR;          // 64 * KSTR
    float* Vs = Ks + 64 * KSTR;           // 64 * KSTR

    const int tid = threadIdx.x;
    const int lane = tid & 31;
    const int w = tid >> 5;
    const int lq = lane >> 2;
    const int lr = lane & 3;

    const int qt = blockIdx.x;
    const int h  = blockIdx.y;
    const int b  = blockIdx.z;
    const int qb = qt * 128;

    const size_t base = (size_t)b * LL * DD + (size_t)h * DH;
    const float* Qg = Q + base;
    const float* Kg = K + base;
    const float* Vg = V + base;
    float* Og = O + base;

    // Load Q tile (pre-scaled by 1/sqrt(64) = 0.125)
    for (int i = tid; i < 128 * 16; i += 128) {
        int r = i >> 4, d4 = (i & 15) * 4;
        float4 qv = *(const float4*)&Qg[(size_t)(qb + r) * DD + d4];
        qv.x *= 0.125f; qv.y *= 0.125f; qv.z *= 0.125f; qv.w *= 0.125f;
        *(float4*)&Qs[r * QSTR + d4] = qv;
    }

    float oacc[2][8][4];
    float m[4], l[4];
#pragma unroll
    for (int j = 0; j < 4; j++) { m[j] = -1e30f; l[j] = 0.0f; }
#pragma unroll
    for (int mi = 0; mi < 2; mi++)
#pragma unroll
        for (int ni = 0; ni < 8; ni++)
#pragma unroll
            for (int q = 0; q < 4; q++) oacc[mi][ni][q] = 0.0f;

    const uint32_t* Qu = (const uint32_t*)Qs;
    const uint32_t* Ku = (const uint32_t*)Ks;
    const uint32_t* Pu = (const uint32_t*)Ps;
    const uint32_t* Vu = (const uint32_t*)Vs;

    const int ntiles = 2 * qt + 2;
    for (int kt = 0; kt < ntiles; kt++) {
        const int kb = kt * 64;

        for (int i = tid; i < 64 * 16; i += 128) {
            int r = i >> 4, d4 = (i & 15) * 4;
            *(float4*)&Ks[r * KSTR + d4] = *(const float4*)&Kg[(size_t)(kb + r) * DD + d4];
            *(float4*)&Vs[r * KSTR + d4] = *(const float4*)&Vg[(size_t)(kb + r) * DD + d4];
        }
        __syncthreads();

        // --- S = Q @ K^T ---
        float sacc[2][8][4];
#pragma unroll
        for (int mi = 0; mi < 2; mi++)
#pragma unroll
            for (int ni = 0; ni < 8; ni++)
#pragma unroll
                for (int q = 0; q < 4; q++) sacc[mi][ni][q] = 0.0f;

#pragma unroll
        for (int k8 = 0; k8 < 8; k8++) {
            uint32_t ah[2][4], al[2][4];
#pragma unroll
            for (int mi = 0; mi < 2; mi++) {
                int r = w * 32 + mi * 16 + lq;
                int c = k8 * 8 + lr;
                tfsplit(Qu[r * QSTR + c],           ah[mi][0], al[mi][0]);
                tfsplit(Qu[(r + 8) * QSTR + c],     ah[mi][1], al[mi][1]);
                tfsplit(Qu[r * QSTR + c + 4],       ah[mi][2], al[mi][2]);
                tfsplit(Qu[(r + 8) * QSTR + c + 4], ah[mi][3], al[mi][3]);
            }
#pragma unroll
            for (int ni = 0; ni < 8; ni++) {
                uint32_t bh[2], bl[2];
                tfsplit(Ku[(ni * 8 + lq) * KSTR + k8 * 8 + lr],     bh[0], bl[0]);
                tfsplit(Ku[(ni * 8 + lq) * KSTR + k8 * 8 + lr + 4], bh[1], bl[1]);
                mma3(sacc[0][ni], ah[0], al[0], bh, bl);
                mma3(sacc[1][ni], ah[1], al[1], bh, bl);
            }
        }

        // --- causal mask ---
        if (kb + 63 > qb) {
#pragma unroll
            for (int mi = 0; mi < 2; mi++)
#pragma unroll
                for (int ni = 0; ni < 8; ni++)
#pragma unroll
                    for (int q = 0; q < 4; q++) {
                        int row_g = qb + w * 32 + mi * 16 + lq + (q >> 1) * 8;
                        int col_g = kb + ni * 8 + lr * 2 + (q & 1);
                        if (col_g > row_g) sacc[mi][ni][q] = -1e30f;
                    }
        }

        // --- online softmax ---
        float rmax[4] = {-1e30f, -1e30f, -1e30f, -1e30f};
#pragma unroll
        for (int mi = 0; mi < 2; mi++)
#pragma unroll
            for (int ni = 0; ni < 8; ni++)
#pragma unroll
                for (int q = 0; q < 4; q++) {
                    int j = mi * 2 + (q >> 1);
                    rmax[j] = fmaxf(rmax[j], sacc[mi][ni][q]);
                }
#pragma unroll
        for (int j = 0; j < 4; j++) {
            rmax[j] = fmaxf(rmax[j], __shfl_xor_sync(0xffffffffu, rmax[j], 1));
            rmax[j] = fmaxf(rmax[j], __shfl_xor_sync(0xffffffffu, rmax[j], 2));
        }

        float sc[4], rs[4];
#pragma unroll
        for (int j = 0; j < 4; j++) {
            float mn = fmaxf(m[j], rmax[j]);
            sc[j] = __expf(m[j] - mn);
            m[j] = mn;
            rs[j] = 0.0f;
        }
#pragma unroll
        for (int mi = 0; mi < 2; mi++)
#pragma unroll
            for (int ni = 0; ni < 8; ni++)
#pragma unroll
                for (int q = 0; q < 4; q++) {
                    int j = mi * 2 + (q >> 1);
                    float p = __expf(sacc[mi][ni][q] - m[j]);
                    sacc[mi][ni][q] = p;
                    rs[j] += p;
                }
#pragma unroll
        for (int j = 0; j < 4; j++) {
            rs[j] += __shfl_xor_sync(0xffffffffu, rs[j], 1);
            rs[j] += __shfl_xor_sync(0xffffffffu, rs[j], 2);
            l[j] = l[j] * sc[j] + rs[j];
        }
#pragma unroll
        for (int mi = 0; mi < 2; mi++)
#pragma unroll
            for (int ni = 0; ni < 8; ni++)
#pragma unroll
                for (int q = 0; q < 4; q++)
                    oacc[mi][ni][q] *= sc[mi * 2 + (q >> 1)];

        // --- stage P to smem ---
#pragma unroll
        for (int mi = 0; mi < 2; mi++)
#pragma unroll
            for (int ni = 0; ni < 8; ni++) {
                int r = w * 32 + mi * 16 + lq;
                int c = ni * 8 + lr * 2;
                *(float2*)&Ps[r * QSTR + c] = make_float2(sacc[mi][ni][0], sacc[mi][ni][1]);
                *(float2*)&Ps[(r + 8) * QSTR + c] = make_float2(sacc[mi][ni][2], sacc[mi][ni][3]);
            }
        __syncwarp();

        // --- O += P @ V ---
#pragma unroll
        for (int k8 = 0; k8 < 8; k8++) {
            uint32_t ah[2][4], al[2][4];
#pragma unroll
            for (int mi = 0; mi < 2; mi++) {
                int r = w * 32 + mi * 16 + lq;
                int c = k8 * 8 + lr;
                tfsplit(Pu[r * QSTR + c],           ah[mi][0], al[mi][0]);
                tfsplit(Pu[(r + 8) * QSTR + c],     ah[mi][1], al[mi][1]);
                tfsplit(Pu[r * QSTR + c + 4],       ah[mi][2], al[mi][2]);
                tfsplit(Pu[(r + 8) * QSTR + c + 4], ah[mi][3], al[mi][3]);
            }
#pragma unroll
            for (int ni = 0; ni < 8; ni++) {
                uint32_t bh[2], bl[2];
                tfsplit(Vu[(k8 * 8 + lr) * KSTR + ni * 8 + lq],       bh[0], bl[0]);
                tfsplit(Vu[(k8 * 8 + lr + 4) * KSTR + ni * 8 + lq],   bh[1], bl[1]);
                mma3(oacc[0][ni], ah[0], al[0], bh, bl);
                mma3(oacc[1][ni], ah[1], al[1], bh, bl);
            }
        }
        __syncthreads();
    }

    // epilogue: normalize + store
    float inv[4];
#pragma unroll
    for (int j = 0; j < 4; j++) inv[j] = 1.0f / l[j];
#pragma unroll
    for (int mi = 0; mi < 2; mi++) {
#pragma unroll
        for (int ni = 0; ni < 8; ni++) {
            int r = qb + w * 32 + mi * 16 + lq;
            int c = ni * 8 + lr * 2;
            *(float2*)&Og[(size_t)r * DD + c] =
                make_float2(oacc[mi][ni][0] * inv[2 * mi], oacc[mi][ni][1] * inv[2 * mi]);
            *(float2*)&Og[(size_t)(r + 8) * DD + c] =
                make_float2(oacc[mi][ni][2] * inv[2 * mi + 1], oacc[mi][ni][3] * inv[2 * mi + 1]);
        }
    }
}

// ---------------------------------------------------------------------------
extern "C" void kernel_launch(void* const* d_in, const int* in_sizes, int n_in,
                              void* d_out, int out_size)
{
    (void)in_sizes; (void)n_in; (void)out_size;
    const float* x    = (const float*)d_in[0];
    const float* Wq   = (const float*)d_in[1];
    const float* Wk   = (const float*)d_in[2];
    const float* Wv   = (const float*)d_in[3];
    const float* Wout = (const float*)d_in[4];
    float* out = (float*)d_out;

    float *q, *k, *v, *o;
    cudaGetSymbolAddress((void**)&q, g_q);
    cudaGetSymbolAddress((void**)&k, g_k);
    cudaGetSymbolAddress((void**)&v, g_v);
    cudaGetSymbolAddress((void**)&o, g_o);

    const int M = BB * LL;   // 4096
    const int N = DD;        // 1024
    const int Kd = DD;       // 1024
    dim3 gg(N / 128, M / 128);

    gemm_tf32<<<gg, 256>>>(x, Wq, q, M, N, Kd);
    gemm_tf32<<<gg, 256>>>(x, Wk, k, M, N, Kd);
    gemm_tf32<<<gg, 256>>>(x, Wv, v, M, N, Kd);

    const int smem_attn = (128 * QSTR * 2 + 64 * KSTR * 2) * 4;  // 106496 B
    cudaFuncSetAttribute(attn_tf32, cudaFuncAttributeMaxDynamicSharedMemorySize, smem_attn);
    dim3 ga(LL / 128, HH, BB);
    attn_tf32<<<ga, 128, smem_attn>>>(q, k, v, o);

    gemm_tf32<<<gg, 256>>>(o, Wout, out, M, N, Kd);
}

// round 7
// speedup vs baseline: 2.5725x; 1.7569x over previous
#include <cuda_runtime.h>
#include <cuda_bf16.h>
#include <math.h>
#include <stdint.h>

// Problem constants
#define BB 2
#define LL 2048
#define DD 1024
#define HH 16
#define DH 64
#define M1 1048576
#define M4 4194304

// One big scratch buffer (bf16), offsets in elements:
//  XH=0, XL=M4, WTQ_H=8M1,WTQ_L=9M1, WTK_H=10M1,WTK_L=11M1, WTV_H=12M1,WTV_L=13M1,
//  WTO_H=14M1,WTO_L=15M1, QH=16M1,QL=20M1, KH=24M1,KL=28M1, VTH=32M1,VTL=36M1,
//  OH=40M1,OL=44M1  -> total 48*M1 elements
__device__ __nv_bfloat16 g_buf[48 * M1];

// ---------------------------------------------------------------------------
// Helpers
// ---------------------------------------------------------------------------
__device__ __forceinline__ uint32_t s2u(const void* p) {
    return (uint32_t)__cvta_generic_to_shared(p);
}

__device__ __forceinline__ void mma_bf16(float* c, const uint32_t* a, const uint32_t* b) {
    asm volatile(
        "mma.sync.aligned.m16n8k16.row.col.f32.bf16.bf16.f32 "
        "{%0,%1,%2,%3}, {%4,%5,%6,%7}, {%8,%9}, {%0,%1,%2,%3};\n"
        : "+f"(c[0]), "+f"(c[1]), "+f"(c[2]), "+f"(c[3])
        : "r"(a[0]), "r"(a[1]), "r"(a[2]), "r"(a[3]), "r"(b[0]), "r"(b[1]));
}

// split pair (x0,x1) -> packed bf16x2 hi (return) and lo (out param)
__device__ __forceinline__ uint32_t packsplit(float x0, float x1, uint32_t& lo_out) {
    __nv_bfloat16 h0 = __float2bfloat16_rn(x0);
    __nv_bfloat16 h1 = __float2bfloat16_rn(x1);
    __nv_bfloat16 l0 = __float2bfloat16_rn(x0 - __bfloat162float(h0));
    __nv_bfloat16 l1 = __float2bfloat16_rn(x1 - __bfloat162float(h1));
    __nv_bfloat162 hp = __halves2bfloat162(h0, h1);   // h0 in low 16 bits
    __nv_bfloat162 lp = __halves2bfloat162(l0, l1);
    lo_out = *(uint32_t*)&lp;
    return *(uint32_t*)&hp;
}

__device__ __forceinline__ void cp_async16(uint32_t dst, const void* src) {
    asm volatile("cp.async.ca.shared.global [%0], [%1], 16;\n" :: "r"(dst), "l"(src));
}
__device__ __forceinline__ void cp_commit() {
    asm volatile("cp.async.commit_group;\n");
}
__device__ __forceinline__ void cp_wait0() {
    asm volatile("cp.async.wait_group 0;\n" ::: "memory");
}

// ---------------------------------------------------------------------------
// Prepass: elementwise fp32 -> bf16 hi/lo split
// ---------------------------------------------------------------------------
__global__ __launch_bounds__(256) void split_kernel(
    const float* __restrict__ in, __nv_bfloat16* __restrict__ hi,
    __nv_bfloat16* __restrict__ lo, int n)
{
    int i = blockIdx.x * 256 + threadIdx.x;
    if (i >= n) return;
    float x = in[i];
    __nv_bfloat16 h = __float2bfloat16_rn(x);
    hi[i] = h;
    lo[i] = __float2bfloat16_rn(x - __bfloat162float(h));
}

// ---------------------------------------------------------------------------
// Prepass: W [1024 in][1024 out] fp32 -> Wt [out][in] bf16 hi/lo
// ---------------------------------------------------------------------------
__global__ __launch_bounds__(256) void wtrans_kernel(
    const float* __restrict__ W, __nv_bfloat16* __restrict__ th,
    __nv_bfloat16* __restrict__ tl)
{
    __shared__ float t[32][33];
    const int tx = threadIdx.x, ty = threadIdx.y;   // 32 x 8
    const int bx = blockIdx.x * 32, by = blockIdx.y * 32;
#pragma unroll
    for (int j = 0; j < 32; j += 8)
        t[ty + j][tx] = W[(size_t)(by + ty + j) * DD + bx + tx];
    __syncthreads();
#pragma unroll
    for (int j = 0; j < 32; j += 8) {
        float x = t[tx][ty + j];   // = W[by+tx][bx+ty+j]
        __nv_bfloat16 h = __float2bfloat16_rn(x);
        size_t o = (size_t)(bx + ty + j) * DD + by + tx;
        th[o] = h;
        tl[o] = __float2bfloat16_rn(x - __bfloat162float(h));
    }
}

// ---------------------------------------------------------------------------
// bf16x3 GEMM: C = A @ Wt^T.  A hi/lo [4096][1024] bf16, Wt hi/lo [1024][1024].
// Block 128x128, K-stage 32, 256 threads = 8 warps (2m x 4n), warp tile 64x32.
// Smem rows: 16 u32 data + stride 20 (conflict-free frag reads).
// Epilogue modes: 0 = fp32 C, 1 = bf16 hi/lo split (alpha applied),
//                 2 = bf16 hi/lo split, transposed per-head (for V).
// ---------------------------------------------------------------------------
#define GST 20
__global__ __launch_bounds__(256) void gemm_bf16(
    const __nv_bfloat16* __restrict__ Ah_g, const __nv_bfloat16* __restrict__ Al_g,
    const __nv_bfloat16* __restrict__ Bh_g, const __nv_bfloat16* __restrict__ Bl_g,
    float* __restrict__ Cf, __nv_bfloat16* __restrict__ Ch, __nv_bfloat16* __restrict__ Cl,
    int mode, float alpha)
{
    extern __shared__ uint32_t sg[];
    uint32_t* Ahs = sg;               // 2 stages x 128*20
    uint32_t* Als = sg + 5120;
    uint32_t* Bhs = sg + 10240;
    uint32_t* Bls = sg + 15360;

    const int tid = threadIdx.x;
    const int lane = tid & 31;
    const int wid = tid >> 5;
    const int warp_m = wid & 1;
    const int warp_n = wid >> 1;
    const int lq = lane >> 2;
    const int lr = lane & 3;

    const int bm = blockIdx.y * 128;
    const int bn = blockIdx.x * 128;

    const uint32_t* Ah4 = (const uint32_t*)Ah_g;
    const uint32_t* Al4 = (const uint32_t*)Al_g;
    const uint32_t* Bh4 = (const uint32_t*)Bh_g;
    const uint32_t* Bl4 = (const uint32_t*)Bl_g;

    float acc[4][4][4];
#pragma unroll
    for (int mi = 0; mi < 4; mi++)
#pragma unroll
        for (int ni = 0; ni < 4; ni++)
#pragma unroll
            for (int q = 0; q < 4; q++) acc[mi][ni][q] = 0.0f;

    const uint32_t sAh = s2u(Ahs), sAl = s2u(Als), sBh = s2u(Bhs), sBl = s2u(Bls);

    auto load = [&](int buf, int k0u) {   // k0u: k offset in u32 (bf16 pairs)
#pragma unroll
        for (int j = 0; j < 2; j++) {
            int c = tid + j * 256;
            int r = c >> 2, q = (c & 3) * 4;
            uint32_t o = (uint32_t)(buf * 2560 + r * GST + q) * 4;
            size_t ao = (size_t)(bm + r) * 512 + k0u + q;
            size_t bo = (size_t)(bn + r) * 512 + k0u + q;
            cp_async16(sAh + o, Ah4 + ao);
            cp_async16(sAl + o, Al4 + ao);
            cp_async16(sBh + o, Bh4 + bo);
            cp_async16(sBl + o, Bl4 + bo);
        }
        cp_commit();
    };

    load(0, 0);
    const int T = DD / 32;   // 32 stages

    for (int t = 0; t < T; t++) {
        cp_wait0();
        __syncthreads();
        if (t + 1 < T) load((t + 1) & 1, (t + 1) * 16);

        const uint32_t* Ah = Ahs + (t & 1) * 2560;
        const uint32_t* Al = Als + (t & 1) * 2560;
        const uint32_t* Bh = Bhs + (t & 1) * 2560;
        const uint32_t* Bl = Bls + (t & 1) * 2560;

#pragma unroll
        for (int kk = 0; kk < 2; kk++) {
            const int kb8 = kk * 8;
            uint32_t ah[4][4], al[4][4];
#pragma unroll
            for (int mi = 0; mi < 4; mi++) {
                int r0 = warp_m * 64 + mi * 16 + lq;
                ah[mi][0] = Ah[r0 * GST + kb8 + lr];
                ah[mi][1] = Ah[(r0 + 8) * GST + kb8 + lr];
                ah[mi][2] = Ah[r0 * GST + kb8 + lr + 4];
                ah[mi][3] = Ah[(r0 + 8) * GST + kb8 + lr + 4];
                al[mi][0] = Al[r0 * GST + kb8 + lr];
                al[mi][1] = Al[(r0 + 8) * GST + kb8 + lr];
                al[mi][2] = Al[r0 * GST + kb8 + lr + 4];
                al[mi][3] = Al[(r0 + 8) * GST + kb8 + lr + 4];
            }
#pragma unroll
            for (int ni = 0; ni < 4; ni++) {
                int br = warp_n * 32 + ni * 8 + lq;
                uint32_t bh[2], bl[2];
                bh[0] = Bh[br * GST + kb8 + lr];
                bh[1] = Bh[br * GST + kb8 + lr + 4];
                bl[0] = Bl[br * GST + kb8 + lr];
                bl[1] = Bl[br * GST + kb8 + lr + 4];
#pragma unroll
                for (int mi = 0; mi < 4; mi++) {
                    mma_bf16(acc[mi][ni], ah[mi], bl);
                    mma_bf16(acc[mi][ni], al[mi], bh);
                    mma_bf16(acc[mi][ni], ah[mi], bh);
                }
            }
        }
        __syncthreads();
    }

    // ---- epilogue ----
    if (mode == 0) {
#pragma unroll
        for (int mi = 0; mi < 4; mi++)
#pragma unroll
            for (int ni = 0; ni < 4; ni++) {
                int r = bm + warp_m * 64 + mi * 16 + lq;
                int cc = bn + warp_n * 32 + ni * 8 + lr * 2;
                *(float2*)&Cf[(size_t)r * DD + cc] = make_float2(acc[mi][ni][0], acc[mi][ni][1]);
                *(float2*)&Cf[(size_t)(r + 8) * DD + cc] = make_float2(acc[mi][ni][2], acc[mi][ni][3]);
            }
    } else if (mode == 1) {
        uint32_t* ChU = (uint32_t*)Ch;
        uint32_t* ClU = (uint32_t*)Cl;
#pragma unroll
        for (int mi = 0; mi < 4; mi++)
#pragma unroll
            for (int ni = 0; ni < 4; ni++) {
                int r = bm + warp_m * 64 + mi * 16 + lq;
                int cc = bn + warp_n * 32 + ni * 8 + lr * 2;
                uint32_t lo, hi;
                hi = packsplit(acc[mi][ni][0] * alpha, acc[mi][ni][1] * alpha, lo);
                ChU[(size_t)r * 512 + (cc >> 1)] = hi;
                ClU[(size_t)r * 512 + (cc >> 1)] = lo;
                hi = packsplit(acc[mi][ni][2] * alpha, acc[mi][ni][3] * alpha, lo);
                ChU[(size_t)(r + 8) * 512 + (cc >> 1)] = hi;
                ClU[(size_t)(r + 8) * 512 + (cc >> 1)] = lo;
            }
    } else {
        // V: transpose per-head: token r, col c=(h,e) -> vt[b][h][e][l]
#pragma unroll
        for (int mi = 0; mi < 4; mi++)
#pragma unroll
            for (int ni = 0; ni < 4; ni++)
#pragma unroll
                for (int q = 0; q < 4; q++) {
                    int r = bm + warp_m * 64 + mi * 16 + lq + (q >> 1) * 8;
                    int cc = bn + warp_n * 32 + ni * 8 + lr * 2 + (q & 1);
                    int hh = cc >> 6, e = cc & 63, bI = r >> 11, l = r & 2047;
                    size_t dst = (((size_t)bI * HH + hh) * DH + e) * LL + l;
                    float x = acc[mi][ni][q];
                    __nv_bfloat16 h = __float2bfloat16_rn(x);
                    Ch[dst] = h;
                    Cl[dst] = __float2bfloat16_rn(x - __bfloat162float(h));
                }
    }
}

// ---------------------------------------------------------------------------
// bf16x3 flash attention, causal. 128 threads (4 warps), BQ=128, BKV=64.
// Q/K pre-split bf16 hi/lo [4096][1024]; V pre-split+transposed [B][H][Dh][L].
// Output: bf16 hi/lo split [4096][1024] (feeds final GEMM).
// Smem rows: 32 u32 data + stride 36 (conflict-free frag reads).
// ---------------------------------------------------------------------------
#define AS 36
__global__ __launch_bounds__(128) void attn_bf16(
    const uint32_t* __restrict__ Qh_g, const uint32_t* __restrict__ Ql_g,
    const uint32_t* __restrict__ Kh_g, const uint32_t* __restrict__ Kl_g,
    const uint32_t* __restrict__ Vh_g, const uint32_t* __restrict__ Vl_g,
    uint32_t* __restrict__ Oh_g, uint32_t* __restrict__ Ol_g)
{
    extern __shared__ uint32_t sm[];
    uint32_t* Qh = sm;              // 128*36 = 4608
    uint32_t* Ql = Qh + 4608;
    uint32_t* Kh = Ql + 4608;       // 64*36 = 2304
    uint32_t* Kl = Kh + 2304;
    uint32_t* Vh = Kl + 2304;
    uint32_t* Vl = Vh + 2304;
    uint32_t* Ph = Vl + 2304;       // 128*36
    uint32_t* Pl = Ph + 4608;       // total 27648 u32 = 110592 B

    const int tid = threadIdx.x;
    const int lane = tid & 31;
    const int w = tid >> 5;
    const int lq = lane >> 2;
    const int lr = lane & 3;

    const int qt = blockIdx.x;
    const int h  = blockIdx.y;
    const int b  = blockIdx.z;
    const int qb = qt * 128;

    // Load Q tile (already scaled by 1/8 in QKV GEMM epilogue)
    for (int i = tid; i < 128 * 32; i += 128) {
        int r = i >> 5, c = i & 31;
        size_t g = (size_t)(b * LL + qb + r) * 512 + h * 32 + c;
        Qh[r * AS + c] = Qh_g[g];
        Ql[r * AS + c] = Ql_g[g];
    }

    float oacc[2][8][4];
    float m[4], l[4];
#pragma unroll
    for (int j = 0; j < 4; j++) { m[j] = -1e30f; l[j] = 0.0f; }
#pragma unroll
    for (int mi = 0; mi < 2; mi++)
#pragma unroll
        for (int ni = 0; ni < 8; ni++)
#pragma unroll
            for (int q = 0; q < 4; q++) oacc[mi][ni][q] = 0.0f;

    const int ntiles = 2 * qt + 2;
    for (int kt = 0; kt < ntiles; kt++) {
        const int kb = kt * 64;

        // Load K (natural [kv][Dh]) and V (transposed [e][L]) tiles
        for (int i = tid; i < 64 * 32; i += 128) {
            int r = i >> 5, c = i & 31;
            size_t gk = (size_t)(b * LL + kb + r) * 512 + h * 32 + c;
            Kh[r * AS + c] = Kh_g[gk];
            Kl[r * AS + c] = Kl_g[gk];
            size_t gv = ((size_t)(b * HH + h) * DH + r) * 1024 + (kb >> 1) + c;
            Vh[r * AS + c] = Vh_g[gv];
            Vl[r * AS + c] = Vl_g[gv];
        }
        __syncthreads();

        // --- S = Q @ K^T ---
        float sacc[2][8][4];
#pragma unroll
        for (int mi = 0; mi < 2; mi++)
#pragma unroll
            for (int ni = 0; ni < 8; ni++)
#pragma unroll
                for (int q = 0; q < 4; q++) sacc[mi][ni][q] = 0.0f;

#pragma unroll
        for (int kk = 0; kk < 4; kk++) {
            const int kb8 = kk * 8;
            uint32_t ah[2][4], al[2][4];
#pragma unroll
            for (int mi = 0; mi < 2; mi++) {
                int r0 = w * 32 + mi * 16 + lq;
                ah[mi][0] = Qh[r0 * AS + kb8 + lr];
                ah[mi][1] = Qh[(r0 + 8) * AS + kb8 + lr];
                ah[mi][2] = Qh[r0 * AS + kb8 + lr + 4];
                ah[mi][3] = Qh[(r0 + 8) * AS + kb8 + lr + 4];
                al[mi][0] = Ql[r0 * AS + kb8 + lr];
                al[mi][1] = Ql[(r0 + 8) * AS + kb8 + lr];
                al[mi][2] = Ql[r0 * AS + kb8 + lr + 4];
                al[mi][3] = Ql[(r0 + 8) * AS + kb8 + lr + 4];
            }
#pragma unroll
            for (int ni = 0; ni < 8; ni++) {
                int kr = ni * 8 + lq;
                uint32_t bh[2], bl[2];
                bh[0] = Kh[kr * AS + kb8 + lr];
                bh[1] = Kh[kr * AS + kb8 + lr + 4];
                bl[0] = Kl[kr * AS + kb8 + lr];
                bl[1] = Kl[kr * AS + kb8 + lr + 4];
                mma_bf16(sacc[0][ni], ah[0], bl);
                mma_bf16(sacc[0][ni], al[0], bh);
                mma_bf16(sacc[0][ni], ah[0], bh);
                mma_bf16(sacc[1][ni], ah[1], bl);
                mma_bf16(sacc[1][ni], al[1], bh);
                mma_bf16(sacc[1][ni], ah[1], bh);
            }
        }

        // --- causal mask ---
        if (kb + 63 > qb) {
#pragma unroll
            for (int mi = 0; mi < 2; mi++)
#pragma unroll
                for (int ni = 0; ni < 8; ni++)
#pragma unroll
                    for (int q = 0; q < 4; q++) {
                        int row_g = qb + w * 32 + mi * 16 + lq + (q >> 1) * 8;
                        int col_g = kb + ni * 8 + lr * 2 + (q & 1);
                        if (col_g > row_g) sacc[mi][ni][q] = -1e30f;
                    }
        }

        // --- online softmax ---
        float rmax[4] = {-1e30f, -1e30f, -1e30f, -1e30f};
#pragma unroll
        for (int mi = 0; mi < 2; mi++)
#pragma unroll
            for (int ni = 0; ni < 8; ni++)
#pragma unroll
                for (int q = 0; q < 4; q++) {
                    int j = mi * 2 + (q >> 1);
                    rmax[j] = fmaxf(rmax[j], sacc[mi][ni][q]);
                }
#pragma unroll
        for (int j = 0; j < 4; j++) {
            rmax[j] = fmaxf(rmax[j], __shfl_xor_sync(0xffffffffu, rmax[j], 1));
            rmax[j] = fmaxf(rmax[j], __shfl_xor_sync(0xffffffffu, rmax[j], 2));
        }

        float sc[4], rs[4];
#pragma unroll
        for (int j = 0; j < 4; j++) {
            float mn = fmaxf(m[j], rmax[j]);
            sc[j] = __expf(m[j] - mn);
            m[j] = mn;
            rs[j] = 0.0f;
        }
#pragma unroll
        for (int mi = 0; mi < 2; mi++)
#pragma unroll
            for (int ni = 0; ni < 8; ni++)
#pragma unroll
                for (int q = 0; q < 4; q++) {
                    int j = mi * 2 + (q >> 1);
                    float p = __expf(sacc[mi][ni][q] - m[j]);
                    sacc[mi][ni][q] = p;
                    rs[j] += p;
                }
#pragma unroll
        for (int j = 0; j < 4; j++) {
            rs[j] += __shfl_xor_sync(0xffffffffu, rs[j], 1);
            rs[j] += __shfl_xor_sync(0xffffffffu, rs[j], 2);
            l[j] = l[j] * sc[j] + rs[j];
        }
#pragma unroll
        for (int mi = 0; mi < 2; mi++)
#pragma unroll
            for (int ni = 0; ni < 8; ni++)
#pragma unroll
                for (int q = 0; q < 4; q++)
                    oacc[mi][ni][q] *= sc[mi * 2 + (q >> 1)];

        // --- stage P (split bf16 hi/lo) to smem ---
#pragma unroll
        for (int mi = 0; mi < 2; mi++)
#pragma unroll
            for (int ni = 0; ni < 8; ni++) {
                int r = w * 32 + mi * 16 + lq;
                int cu = ni * 4 + lr;
                uint32_t lo, hi;
                hi = packsplit(sacc[mi][ni][0], sacc[mi][ni][1], lo);
                Ph[r * AS + cu] = hi;
                Pl[r * AS + cu] = lo;
                hi = packsplit(sacc[mi][ni][2], sacc[mi][ni][3], lo);
                Ph[(r + 8) * AS + cu] = hi;
                Pl[(r + 8) * AS + cu] = lo;
            }
        __syncwarp();

        // --- O += P @ V ---
#pragma unroll
        for (int kk = 0; kk < 4; kk++) {
            const int kb8 = kk * 8;
            uint32_t ah[2][4], al[2][4];
#pragma unroll
            for (int mi = 0; mi < 2; mi++) {
                int r0 = w * 32 + mi * 16 + lq;
                ah[mi][0] = Ph[r0 * AS + kb8 + lr];
                ah[mi][1] = Ph[(r0 + 8) * AS + kb8 + lr];
                ah[mi][2] = Ph[r0 * AS + kb8 + lr + 4];
                ah[mi][3] = Ph[(r0 + 8) * AS + kb8 + lr + 4];
                al[mi][0] = Pl[r0 * AS + kb8 + lr];
                al[mi][1] = Pl[(r0 + 8) * AS + kb8 + lr];
                al[mi][2] = Pl[r0 * AS + kb8 + lr + 4];
                al[mi][3] = Pl[(r0 + 8) * AS + kb8 + lr + 4];
            }
#pragma unroll
            for (int ni = 0; ni < 8; ni++) {
                int vr = ni * 8 + lq;
                uint32_t bh[2], bl[2];
                bh[0] = Vh[vr * AS + kb8 + lr];
                bh[1] = Vh[vr * AS + kb8 + lr + 4];
                bl[0] = Vl[vr * AS + kb8 + lr];
                bl[1] = Vl[vr * AS + kb8 + lr + 4];
                mma_bf16(oacc[0][ni], ah[0], bl);
                mma_bf16(oacc[0][ni], al[0], bh);
                mma_bf16(oacc[0][ni], ah[0], bh);
                mma_bf16(oacc[1][ni], ah[1], bl);
                mma_bf16(oacc[1][ni], al[1], bh);
                mma_bf16(oacc[1][ni], ah[1], bh);
            }
        }
        __syncthreads();
    }

    // epilogue: normalize + split-store O
    float inv[4];
#pragma unroll
    for (int j = 0; j < 4; j++) inv[j] = 1.0f / l[j];
#pragma unroll
    for (int mi = 0; mi < 2; mi++) {
#pragma unroll
        for (int ni = 0; ni < 8; ni++) {
            int r = w * 32 + mi * 16 + lq;
            int cu = ni * 4 + lr;
            size_t g0 = (size_t)(b * LL + qb + r) * 512 + h * 32 + cu;
            size_t g1 = (size_t)(b * LL + qb + r + 8) * 512 + h * 32 + cu;
            uint32_t lo, hi;
            hi = packsplit(oacc[mi][ni][0] * inv[2 * mi], oacc[mi][ni][1] * inv[2 * mi], lo);
            Oh_g[g0] = hi; Ol_g[g0] = lo;
            hi = packsplit(oacc[mi][ni][2] * inv[2 * mi + 1], oacc[mi][ni][3] * inv[2 * mi + 1], lo);
            Oh_g[g1] = hi; Ol_g[g1] = lo;
        }
    }
}

// ---------------------------------------------------------------------------
extern "C" void kernel_launch(void* const* d_in, const int* in_sizes, int n_in,
                              void* d_out, int out_size)
{
    (void)in_sizes; (void)n_in; (void)out_size;
    const float* x    = (const float*)d_in[0];
    const float* Wq   = (const float*)d_in[1];
    const float* Wk   = (const float*)d_in[2];
    const float* Wv   = (const float*)d_in[3];
    const float* Wout = (const float*)d_in[4];
    float* out = (float*)d_out;

    __nv_bfloat16* g;
    cudaGetSymbolAddress((void**)&g, g_buf);

    __nv_bfloat16* xh  = g;
    __nv_bfloat16* xl  = g + M4;
    __nv_bfloat16* wqh = g + 8 * (size_t)M1;
    __nv_bfloat16* wql = g + 9 * (size_t)M1;
    __nv_bfloat16* wkh = g + 10 * (size_t)M1;
    __nv_bfloat16* wkl = g + 11 * (size_t)M1;
    __nv_bfloat16* wvh = g + 12 * (size_t)M1;
    __nv_bfloat16* wvl = g + 13 * (size_t)M1;
    __nv_bfloat16* woh = g + 14 * (size_t)M1;
    __nv_bfloat16* wol = g + 15 * (size_t)M1;
    __nv_bfloat16* qh  = g + 16 * (size_t)M1;
    __nv_bfloat16* ql  = g + 20 * (size_t)M1;
    __nv_bfloat16* kh  = g + 24 * (size_t)M1;
    __nv_bfloat16* kl  = g + 28 * (size_t)M1;
    __nv_bfloat16* vth = g + 32 * (size_t)M1;
    __nv_bfloat16* vtl = g + 36 * (size_t)M1;
    __nv_bfloat16* oh  = g + 40 * (size_t)M1;
    __nv_bfloat16* ol  = g + 44 * (size_t)M1;

    // Prepasses
    split_kernel<<<M4 / 256, 256>>>(x, xh, xl, M4);
    dim3 wtb(32, 8), wtg(32, 32);
    wtrans_kernel<<<wtg, wtb>>>(Wq, wqh, wql);
    wtrans_kernel<<<wtg, wtb>>>(Wk, wkh, wkl);
    wtrans_kernel<<<wtg, wtb>>>(Wv, wvh, wvl);
    wtrans_kernel<<<wtg, wtb>>>(Wout, woh, wol);

    const int gemm_smem = 20480 * 4;   // 81920 B
    cudaFuncSetAttribute(gemm_bf16, cudaFuncAttributeMaxDynamicSharedMemorySize, gemm_smem);
    dim3 gg(DD / 128, (BB * LL) / 128);   // 8 x 32

    gemm_bf16<<<gg, 256, gemm_smem>>>(xh, xl, wqh, wql, nullptr, qh, ql, 1, 0.125f);
    gemm_bf16<<<gg, 256, gemm_smem>>>(xh, xl, wkh, wkl, nullptr, kh, kl, 1, 1.0f);
    gemm_bf16<<<gg, 256, gemm_smem>>>(xh, xl, wvh, wvl, nullptr, vth, vtl, 2, 1.0f);

    const int attn_smem = 27648 * 4;   // 110592 B
    cudaFuncSetAttribute(attn_bf16, cudaFuncAttributeMaxDynamicSharedMemorySize, attn_smem);
    dim3 ga(LL / 128, HH, BB);
    attn_bf16<<<ga, 128, attn_smem>>>(
        (const uint32_t*)qh, (const uint32_t*)ql,
        (const uint32_t*)kh, (const uint32_t*)kl,
        (const uint32_t*)vth, (const uint32_t*)vtl,
        (uint32_t*)oh, (uint32_t*)ol);

    gemm_bf16<<<gg, 256, gemm_smem>>>(oh, ol, woh, wol, out, nullptr, nullptr, 0, 1.0f);
}

// round 8
// speedup vs baseline: 3.1431x; 1.2218x over previous
#include <cuda_runtime.h>
#include <cuda_bf16.h>
#include <math.h>
#include <stdint.h>

// Problem constants
#define BB 2
#define LL 2048
#define DD 1024
#define HH 16
#define DH 64
#define M1 1048576
#define M4 4194304

// One big scratch buffer (bf16), element offsets documented in kernel_launch.
__device__ __nv_bfloat16 g_buf[48 * M1];

// ---------------------------------------------------------------------------
// Helpers
// ---------------------------------------------------------------------------
__device__ __forceinline__ uint32_t s2u(const void* p) {
    return (uint32_t)__cvta_generic_to_shared(p);
}

__device__ __forceinline__ void mma_bf16(float* c, const uint32_t* a, const uint32_t* b) {
    asm volatile(
        "mma.sync.aligned.m16n8k16.row.col.f32.bf16.bf16.f32 "
        "{%0,%1,%2,%3}, {%4,%5,%6,%7}, {%8,%9}, {%0,%1,%2,%3};\n"
        : "+f"(c[0]), "+f"(c[1]), "+f"(c[2]), "+f"(c[3])
        : "r"(a[0]), "r"(a[1]), "r"(a[2]), "r"(a[3]), "r"(b[0]), "r"(b[1]));
}

__device__ __forceinline__ void mma3(float* c, const uint32_t* ah, const uint32_t* al,
                                     const uint32_t* bh, const uint32_t* bl) {
    mma_bf16(c, al, bh);
    mma_bf16(c, ah, bl);
    mma_bf16(c, ah, bh);
}

__device__ __forceinline__ void ldsm4(uint32_t& r0, uint32_t& r1, uint32_t& r2, uint32_t& r3,
                                      uint32_t addr) {
    asm volatile("ldmatrix.sync.aligned.m8n8.x4.shared.b16 {%0,%1,%2,%3}, [%4];\n"
                 : "=r"(r0), "=r"(r1), "=r"(r2), "=r"(r3) : "r"(addr));
}

// split pair (x0,x1) -> packed bf16x2 hi (return) and lo (out param)
__device__ __forceinline__ uint32_t packsplit(float x0, float x1, uint32_t& lo_out) {
    __nv_bfloat16 h0 = __float2bfloat16_rn(x0);
    __nv_bfloat16 h1 = __float2bfloat16_rn(x1);
    __nv_bfloat16 l0 = __float2bfloat16_rn(x0 - __bfloat162float(h0));
    __nv_bfloat16 l1 = __float2bfloat16_rn(x1 - __bfloat162float(h1));
    __nv_bfloat162 hp = __halves2bfloat162(h0, h1);
    __nv_bfloat162 lp = __halves2bfloat162(l0, l1);
    lo_out = *(uint32_t*)&lp;
    return *(uint32_t*)&hp;
}

__device__ __forceinline__ void cp_async16(uint32_t dst, const void* src) {
    asm volatile("cp.async.ca.shared.global [%0], [%1], 16;\n" :: "r"(dst), "l"(src));
}
__device__ __forceinline__ void cp_commit() {
    asm volatile("cp.async.commit_group;\n");
}
__device__ __forceinline__ void cp_wait0() {
    asm volatile("cp.async.wait_group 0;\n" ::: "memory");
}

// ---------------------------------------------------------------------------
// Prepass: elementwise fp32 -> bf16 hi/lo split
// ---------------------------------------------------------------------------
__global__ __launch_bounds__(256) void split_kernel(
    const float* __restrict__ in, __nv_bfloat16* __restrict__ hi,
    __nv_bfloat16* __restrict__ lo, int n)
{
    int i = blockIdx.x * 256 + threadIdx.x;
    if (i >= n) return;
    float x = in[i];
    __nv_bfloat16 h = __float2bfloat16_rn(x);
    hi[i] = h;
    lo[i] = __float2bfloat16_rn(x - __bfloat162float(h));
}

// ---------------------------------------------------------------------------
// Prepass: W [1024 in][1024 out] fp32 -> Wt [out][in] bf16 hi/lo
// ---------------------------------------------------------------------------
__global__ __launch_bounds__(256) void wtrans_kernel(
    const float* __restrict__ W, __nv_bfloat16* __restrict__ th,
    __nv_bfloat16* __restrict__ tl)
{
    __shared__ float t[32][33];
    const int tx = threadIdx.x, ty = threadIdx.y;   // 32 x 8
    const int bx = blockIdx.x * 32, by = blockIdx.y * 32;
#pragma unroll
    for (int j = 0; j < 32; j += 8)
        t[ty + j][tx] = W[(size_t)(by + ty + j) * DD + bx + tx];
    __syncthreads();
#pragma unroll
    for (int j = 0; j < 32; j += 8) {
        float x = t[tx][ty + j];
        __nv_bfloat16 h = __float2bfloat16_rn(x);
        size_t o = (size_t)(bx + ty + j) * DD + by + tx;
        th[o] = h;
        tl[o] = __float2bfloat16_rn(x - __bfloat162float(h));
    }
}

// ---------------------------------------------------------------------------
// bf16x3 GEMM: C = A @ Wt^T.  A hi/lo [4096][1024], Wt hi/lo [1024][1024].
// 128x128 block, K-stage 32, 8 warps (2m x 4n), warp tile 64x32, ldmatrix.
// Epilogue: 0 = fp32 C, 1 = split bf16 (alpha), 2 = split + per-head transpose.
// ---------------------------------------------------------------------------
#define GST 20
__global__ __launch_bounds__(256) void gemm_bf16(
    const __nv_bfloat16* __restrict__ Ah_g, const __nv_bfloat16* __restrict__ Al_g,
    const __nv_bfloat16* __restrict__ Bh_g, const __nv_bfloat16* __restrict__ Bl_g,
    float* __restrict__ Cf, __nv_bfloat16* __restrict__ Ch, __nv_bfloat16* __restrict__ Cl,
    int mode, float alpha)
{
    extern __shared__ uint32_t sg[];
    uint32_t* Ahs = sg;               // 2 stages x 128*GST
    uint32_t* Als = sg + 5120;
    uint32_t* Bhs = sg + 10240;
    uint32_t* Bls = sg + 15360;

    const int tid = threadIdx.x;
    const int lane = tid & 31;
    const int wid = tid >> 5;
    const int warp_m = wid & 1;
    const int warp_n = wid >> 1;
    const int lq = lane >> 2;
    const int lr = lane & 3;
    const int l8 = lane & 7, lb3 = (lane >> 3) & 1, lb4 = lane >> 4;

    const int bm = blockIdx.y * 128;
    const int bn = blockIdx.x * 128;

    const uint32_t* Ah4 = (const uint32_t*)Ah_g;
    const uint32_t* Al4 = (const uint32_t*)Al_g;
    const uint32_t* Bh4 = (const uint32_t*)Bh_g;
    const uint32_t* Bl4 = (const uint32_t*)Bl_g;

    float acc[4][4][4];
#pragma unroll
    for (int mi = 0; mi < 4; mi++)
#pragma unroll
        for (int ni = 0; ni < 4; ni++)
#pragma unroll
            for (int q = 0; q < 4; q++) acc[mi][ni][q] = 0.0f;

    const uint32_t sAh = s2u(Ahs), sAl = s2u(Als), sBh = s2u(Bhs), sBl = s2u(Bls);

    // ldmatrix per-thread offsets (u32 units)
    const uint32_t a_off = (uint32_t)((warp_m * 64 + l8 + lb3 * 8) * GST + lb4 * 4);
    const uint32_t b_off = (uint32_t)((warp_n * 32 + l8 + lb4 * 8) * GST + lb3 * 4);

    auto load = [&](int buf, int k0u) {
#pragma unroll
        for (int j = 0; j < 2; j++) {
            int c = tid + j * 256;
            int r = c >> 2, q = (c & 3) * 4;
            uint32_t o = (uint32_t)(buf * 2560 + r * GST + q) * 4;
            size_t ao = (size_t)(bm + r) * 512 + k0u + q;
            size_t bo = (size_t)(bn + r) * 512 + k0u + q;
            cp_async16(sAh + o, Ah4 + ao);
            cp_async16(sAl + o, Al4 + ao);
            cp_async16(sBh + o, Bh4 + bo);
            cp_async16(sBl + o, Bl4 + bo);
        }
        cp_commit();
    };

    load(0, 0);
    const int T = DD / 32;

    for (int t = 0; t < T; t++) {
        cp_wait0();
        __syncthreads();
        if (t + 1 < T) load((t + 1) & 1, (t + 1) * 16);

        const uint32_t stg = (uint32_t)(t & 1) * 2560 * 4;

#pragma unroll
        for (int kk = 0; kk < 2; kk++) {
            const uint32_t kb8 = kk * 8 * 4;
            uint32_t ah[4][4], al[4][4];
#pragma unroll
            for (int mi = 0; mi < 4; mi++) {
                uint32_t ad = stg + (a_off + mi * 16 * GST) * 4 + kb8;
                ldsm4(ah[mi][0], ah[mi][1], ah[mi][2], ah[mi][3], sAh + ad);
                ldsm4(al[mi][0], al[mi][1], al[mi][2], al[mi][3], sAl + ad);
            }
#pragma unroll
            for (int p = 0; p < 2; p++) {
                uint32_t bh[4], bl[4];
                uint32_t bd = stg + (b_off + p * 16 * GST) * 4 + kb8;
                ldsm4(bh[0], bh[1], bh[2], bh[3], sBh + bd);
                ldsm4(bl[0], bl[1], bl[2], bl[3], sBl + bd);
#pragma unroll
                for (int mi = 0; mi < 4; mi++) {
                    mma3(acc[mi][2 * p],     ah[mi], al[mi], &bh[0], &bl[0]);
                    mma3(acc[mi][2 * p + 1], ah[mi], al[mi], &bh[2], &bl[2]);
                }
            }
        }
        __syncthreads();
    }

    // ---- epilogue ----
    if (mode == 0) {
#pragma unroll
        for (int mi = 0; mi < 4; mi++)
#pragma unroll
            for (int ni = 0; ni < 4; ni++) {
                int r = bm + warp_m * 64 + mi * 16 + lq;
                int cc = bn + warp_n * 32 + ni * 8 + lr * 2;
                *(float2*)&Cf[(size_t)r * DD + cc] = make_float2(acc[mi][ni][0], acc[mi][ni][1]);
                *(float2*)&Cf[(size_t)(r + 8) * DD + cc] = make_float2(acc[mi][ni][2], acc[mi][ni][3]);
            }
    } else if (mode == 1) {
        uint32_t* ChU = (uint32_t*)Ch;
        uint32_t* ClU = (uint32_t*)Cl;
#pragma unroll
        for (int mi = 0; mi < 4; mi++)
#pragma unroll
            for (int ni = 0; ni < 4; ni++) {
                int r = bm + warp_m * 64 + mi * 16 + lq;
                int cc = bn + warp_n * 32 + ni * 8 + lr * 2;
                uint32_t lo, hi;
                hi = packsplit(acc[mi][ni][0] * alpha, acc[mi][ni][1] * alpha, lo);
                ChU[(size_t)r * 512 + (cc >> 1)] = hi;
                ClU[(size_t)r * 512 + (cc >> 1)] = lo;
                hi = packsplit(acc[mi][ni][2] * alpha, acc[mi][ni][3] * alpha, lo);
                ChU[(size_t)(r + 8) * 512 + (cc >> 1)] = hi;
                ClU[(size_t)(r + 8) * 512 + (cc >> 1)] = lo;
            }
    } else {
        // V: token r, col c=(h,e) -> vt[b][h][e][l]
#pragma unroll
        for (int mi = 0; mi < 4; mi++)
#pragma unroll
            for (int ni = 0; ni < 4; ni++)
#pragma unroll
                for (int q = 0; q < 4; q++) {
                    int r = bm + warp_m * 64 + mi * 16 + lq + (q >> 1) * 8;
                    int cc = bn + warp_n * 32 + ni * 8 + lr * 2 + (q & 1);
                    int hh = cc >> 6, e = cc & 63, bI = r >> 11, l = r & 2047;
                    size_t dst = (((size_t)bI * HH + hh) * DH + e) * LL + l;
                    float x = acc[mi][ni][q];
                    __nv_bfloat16 h = __float2bfloat16_rn(x);
                    Ch[dst] = h;
                    Cl[dst] = __float2bfloat16_rn(x - __bfloat162float(h));
                }
    }
}

// ---------------------------------------------------------------------------
// bf16x3 flash attention, causal. 128 threads (4 warps), BQ=128, BKV=64.
// Q/K pre-split [4096][1024]; V pre-split + per-head transposed [B][H][Dh][L].
// P kept in registers (C-frag == A-frag layout). K/V double-buffered cp.async.
// qt reversed so heavy causal tiles launch first.
// ---------------------------------------------------------------------------
#define AS 36
__global__ __launch_bounds__(128) void attn_bf16(
    const uint32_t* __restrict__ Qh_g, const uint32_t* __restrict__ Ql_g,
    const uint32_t* __restrict__ Kh_g, const uint32_t* __restrict__ Kl_g,
    const uint32_t* __restrict__ Vh_g, const uint32_t* __restrict__ Vl_g,
    uint32_t* __restrict__ Oh_g, uint32_t* __restrict__ Ol_g)
{
    extern __shared__ uint32_t sm[];
    uint32_t* Qh = sm;               // 128*AS = 4608
    uint32_t* Ql = Qh + 4608;
    uint32_t* KV = Ql + 4608;        // 2 stages x [Kh|Kl|Vh|Vl] x 64*AS(2304)
    // stage s base: KV + s*9216; within: Kh 0, Kl 2304, Vh 4608, Vl 6912
    // total smem: 9216 + 18432 = 27648 u32 = 110592... no: 4608*2 + 2304*8 = 27648? 
    // 9216 (Q) + 2*9216 (KV) = 27648 u32 = 110592 B? -> fits 227KB, 2 CTAs = 221KB.

    const int tid = threadIdx.x;
    const int lane = tid & 31;
    const int w = tid >> 5;
    const int lq = lane >> 2;
    const int lr = lane & 3;
    const int l8 = lane & 7, lb3 = (lane >> 3) & 1, lb4 = lane >> 4;

    const int qt = (int)(gridDim.x - 1) - (int)blockIdx.x;   // heavy tiles first
    const int h  = blockIdx.y;
    const int b  = blockIdx.z;
    const int qb = qt * 128;

    const uint32_t sQh = s2u(Qh), sQl = s2u(Ql), sKV = s2u(KV);

    // ldmatrix per-thread offsets (u32 units)
    const uint32_t q_off = (uint32_t)((w * 32 + l8 + lb3 * 8) * AS + lb4 * 4);
    const uint32_t kv_off = (uint32_t)((l8 + lb4 * 8) * AS + lb3 * 4);

    // ---- issue Q loads ----
#pragma unroll
    for (int j = 0; j < 8; j++) {
        int idx = tid + j * 128;          // 0..1023
        int r = idx >> 3, cq = (idx & 7) * 4;
        size_t g = (size_t)(b * LL + qb + r) * 512 + h * 32 + cq;
        uint32_t o = (uint32_t)(r * AS + cq) * 4;
        cp_async16(sQh + o, Qh_g + g);
        cp_async16(sQl + o, Ql_g + g);
    }
    cp_commit();

    auto load_kv = [&](int buf, int kb) {
        uint32_t base = sKV + (uint32_t)buf * 9216 * 4;
#pragma unroll
        for (int j = 0; j < 4; j++) {
            int idx = tid + j * 128;      // 0..511
            int r = idx >> 3, cq = (idx & 7) * 4;
            uint32_t o = (uint32_t)(r * AS + cq) * 4;
            size_t gk = (size_t)(b * LL + kb + r) * 512 + h * 32 + cq;
            cp_async16(base + o,            Kh_g + gk);
            cp_async16(base + 2304 * 4 + o, Kl_g + gk);
            size_t gv = ((size_t)(b * HH + h) * DH + r) * 1024 + (kb >> 1) + cq;
            cp_async16(base + 4608 * 4 + o, Vh_g + gv);
            cp_async16(base + 6912 * 4 + o, Vl_g + gv);
        }
        cp_commit();
    };

    load_kv(0, 0);

    float oacc[2][8][4];
    float m[4], l[4];
#pragma unroll
    for (int j = 0; j < 4; j++) { m[j] = -1e30f; l[j] = 0.0f; }
#pragma unroll
    for (int mi = 0; mi < 2; mi++)
#pragma unroll
        for (int ni = 0; ni < 8; ni++)
#pragma unroll
            for (int q = 0; q < 4; q++) oacc[mi][ni][q] = 0.0f;

    const int ntiles = 2 * qt + 2;
    for (int kt = 0; kt < ntiles; kt++) {
        const int kb = kt * 64;
        cp_wait0();
        __syncthreads();
        if (kt + 1 < ntiles) load_kv((kt + 1) & 1, (kt + 1) * 64);

        const uint32_t kvb = sKV + (uint32_t)(kt & 1) * 9216 * 4;
        const uint32_t sKh = kvb, sKl = kvb + 2304 * 4;
        const uint32_t sVh = kvb + 4608 * 4, sVl = kvb + 6912 * 4;

        // --- S = Q @ K^T ---
        float sacc[2][8][4];
#pragma unroll
        for (int mi = 0; mi < 2; mi++)
#pragma unroll
            for (int ni = 0; ni < 8; ni++)
#pragma unroll
                for (int q = 0; q < 4; q++) sacc[mi][ni][q] = 0.0f;

#pragma unroll
        for (int kk = 0; kk < 4; kk++) {
            const uint32_t kb8 = kk * 8 * 4;
            uint32_t ah[2][4], al[2][4];
#pragma unroll
            for (int mi = 0; mi < 2; mi++) {
                uint32_t ad = (q_off + mi * 16 * AS) * 4 + kb8;
                ldsm4(ah[mi][0], ah[mi][1], ah[mi][2], ah[mi][3], sQh + ad);
                ldsm4(al[mi][0], al[mi][1], al[mi][2], al[mi][3], sQl + ad);
            }
#pragma unroll
            for (int p = 0; p < 4; p++) {
                uint32_t bh[4], bl[4];
                uint32_t bd = (kv_off + p * 16 * AS) * 4 + kb8;
                ldsm4(bh[0], bh[1], bh[2], bh[3], sKh + bd);
                ldsm4(bl[0], bl[1], bl[2], bl[3], sKl + bd);
#pragma unroll
                for (int mi = 0; mi < 2; mi++) {
                    mma3(sacc[mi][2 * p],     ah[mi], al[mi], &bh[0], &bl[0]);
                    mma3(sacc[mi][2 * p + 1], ah[mi], al[mi], &bh[2], &bl[2]);
                }
            }
        }

        // --- causal mask ---
        if (kb + 63 > qb) {
#pragma unroll
            for (int mi = 0; mi < 2; mi++)
#pragma unroll
                for (int ni = 0; ni < 8; ni++)
#pragma unroll
                    for (int q = 0; q < 4; q++) {
                        int row_g = qb + w * 32 + mi * 16 + lq + (q >> 1) * 8;
                        int col_g = kb + ni * 8 + lr * 2 + (q & 1);
                        if (col_g > row_g) sacc[mi][ni][q] = -1e30f;
                    }
        }

        // --- online softmax ---
        float rmax[4] = {-1e30f, -1e30f, -1e30f, -1e30f};
#pragma unroll
        for (int mi = 0; mi < 2; mi++)
#pragma unroll
            for (int ni = 0; ni < 8; ni++)
#pragma unroll
                for (int q = 0; q < 4; q++) {
                    int j = mi * 2 + (q >> 1);
                    rmax[j] = fmaxf(rmax[j], sacc[mi][ni][q]);
                }
#pragma unroll
        for (int j = 0; j < 4; j++) {
            rmax[j] = fmaxf(rmax[j], __shfl_xor_sync(0xffffffffu, rmax[j], 1));
            rmax[j] = fmaxf(rmax[j], __shfl_xor_sync(0xffffffffu, rmax[j], 2));
        }

        float sc[4], rs[4];
#pragma unroll
        for (int j = 0; j < 4; j++) {
            float mn = fmaxf(m[j], rmax[j]);
            sc[j] = __expf(m[j] - mn);
            m[j] = mn;
            rs[j] = 0.0f;
        }
#pragma unroll
        for (int mi = 0; mi < 2; mi++)
#pragma unroll
            for (int ni = 0; ni < 8; ni++)
#pragma unroll
                for (int q = 0; q < 4; q++) {
                    int j = mi * 2 + (q >> 1);
                    float p = __expf(sacc[mi][ni][q] - m[j]);
                    sacc[mi][ni][q] = p;
                    rs[j] += p;
                }
#pragma unroll
        for (int j = 0; j < 4; j++) {
            rs[j] += __shfl_xor_sync(0xffffffffu, rs[j], 1);
            rs[j] += __shfl_xor_sync(0xffffffffu, rs[j], 2);
            l[j] = l[j] * sc[j] + rs[j];
        }
#pragma unroll
        for (int mi = 0; mi < 2; mi++)
#pragma unroll
            for (int ni = 0; ni < 8; ni++)
#pragma unroll
                for (int q = 0; q < 4; q++)
                    oacc[mi][ni][q] *= sc[mi * 2 + (q >> 1)];

        // --- O += P @ V, P fragments formed in registers from sacc ---
#pragma unroll
        for (int kk = 0; kk < 4; kk++) {
            uint32_t ph[2][4], pl[2][4];
#pragma unroll
            for (int mi = 0; mi < 2; mi++) {
                ph[mi][0] = packsplit(sacc[mi][2 * kk][0],     sacc[mi][2 * kk][1],     pl[mi][0]);
                ph[mi][1] = packsplit(sacc[mi][2 * kk][2],     sacc[mi][2 * kk][3],     pl[mi][1]);
                ph[mi][2] = packsplit(sacc[mi][2 * kk + 1][0], sacc[mi][2 * kk + 1][1], pl[mi][2]);
                ph[mi][3] = packsplit(sacc[mi][2 * kk + 1][2], sacc[mi][2 * kk + 1][3], pl[mi][3]);
            }
            const uint32_t kb8 = kk * 8 * 4;
#pragma unroll
            for (int p = 0; p < 4; p++) {
                uint32_t bh[4], bl[4];
                uint32_t bd = (kv_off + p * 16 * AS) * 4 + kb8;
                ldsm4(bh[0], bh[1], bh[2], bh[3], sVh + bd);
                ldsm4(bl[0], bl[1], bl[2], bl[3], sVl + bd);
#pragma unroll
                for (int mi = 0; mi < 2; mi++) {
                    mma3(oacc[mi][2 * p],     ph[mi], pl[mi], &bh[0], &bl[0]);
                    mma3(oacc[mi][2 * p + 1], ph[mi], pl[mi], &bh[2], &bl[2]);
                }
            }
        }
        __syncthreads();
    }

    // epilogue: normalize + split-store O
    float inv[4];
#pragma unroll
    for (int j = 0; j < 4; j++) inv[j] = 1.0f / l[j];
#pragma unroll
    for (int mi = 0; mi < 2; mi++) {
#pragma unroll
        for (int ni = 0; ni < 8; ni++) {
            int r = w * 32 + mi * 16 + lq;
            int cu = ni * 4 + lr;
            size_t g0 = (size_t)(b * LL + qb + r) * 512 + h * 32 + cu;
            size_t g1 = (size_t)(b * LL + qb + r + 8) * 512 + h * 32 + cu;
            uint32_t lo, hi;
            hi = packsplit(oacc[mi][ni][0] * inv[2 * mi], oacc[mi][ni][1] * inv[2 * mi], lo);
            Oh_g[g0] = hi; Ol_g[g0] = lo;
            hi = packsplit(oacc[mi][ni][2] * inv[2 * mi + 1], oacc[mi][ni][3] * inv[2 * mi + 1], lo);
            Oh_g[g1] = hi; Ol_g[g1] = lo;
        }
    }
}

// ---------------------------------------------------------------------------
extern "C" void kernel_launch(void* const* d_in, const int* in_sizes, int n_in,
                              void* d_out, int out_size)
{
    (void)in_sizes; (void)n_in; (void)out_size;
    const float* x    = (const float*)d_in[0];
    const float* Wq   = (const float*)d_in[1];
    const float* Wk   = (const float*)d_in[2];
    const float* Wv   = (const float*)d_in[3];
    const float* Wout = (const float*)d_in[4];
    float* out = (float*)d_out;

    __nv_bfloat16* g;
    cudaGetSymbolAddress((void**)&g, g_buf);

    __nv_bfloat16* xh  = g;
    __nv_bfloat16* xl  = g + M4;
    __nv_bfloat16* wqh = g + 8 * (size_t)M1;
    __nv_bfloat16* wql = g + 9 * (size_t)M1;
    __nv_bfloat16* wkh = g + 10 * (size_t)M1;
    __nv_bfloat16* wkl = g + 11 * (size_t)M1;
    __nv_bfloat16* wvh = g + 12 * (size_t)M1;
    __nv_bfloat16* wvl = g + 13 * (size_t)M1;
    __nv_bfloat16* woh = g + 14 * (size_t)M1;
    __nv_bfloat16* wol = g + 15 * (size_t)M1;
    __nv_bfloat16* qh  = g + 16 * (size_t)M1;
    __nv_bfloat16* ql  = g + 20 * (size_t)M1;
    __nv_bfloat16* kh  = g + 24 * (size_t)M1;
    __nv_bfloat16* kl  = g + 28 * (size_t)M1;
    __nv_bfloat16* vth = g + 32 * (size_t)M1;
    __nv_bfloat16* vtl = g + 36 * (size_t)M1;
    __nv_bfloat16* oh  = g + 40 * (size_t)M1;
    __nv_bfloat16* ol  = g + 44 * (size_t)M1;

    // Prepasses
    split_kernel<<<M4 / 256, 256>>>(x, xh, xl, M4);
    dim3 wtb(32, 8), wtg(32, 32);
    wtrans_kernel<<<wtg, wtb>>>(Wq, wqh, wql);
    wtrans_kernel<<<wtg, wtb>>>(Wk, wkh, wkl);
    wtrans_kernel<<<wtg, wtb>>>(Wv, wvh, wvl);
    wtrans_kernel<<<wtg, wtb>>>(Wout, woh, wol);

    const int gemm_smem = 20480 * 4;
    cudaFuncSetAttribute(gemm_bf16, cudaFuncAttributeMaxDynamicSharedMemorySize, gemm_smem);
    dim3 gg(DD / 128, (BB * LL) / 128);

    gemm_bf16<<<gg, 256, gemm_smem>>>(xh, xl, wqh, wql, nullptr, qh, ql, 1, 0.125f);
    gemm_bf16<<<gg, 256, gemm_smem>>>(xh, xl, wkh, wkl, nullptr, kh, kl, 1, 1.0f);
    gemm_bf16<<<gg, 256, gemm_smem>>>(xh, xl, wvh, wvl, nullptr, vth, vtl, 2, 1.0f);

    const int attn_smem = (4608 * 2 + 9216 * 2) * 4;   // 110592 B
    cudaFuncSetAttribute(attn_bf16, cudaFuncAttributeMaxDynamicSharedMemorySize, attn_smem);
    dim3 ga(LL / 128, HH, BB);
    attn_bf16<<<ga, 128, attn_smem>>>(
        (const uint32_t*)qh, (const uint32_t*)ql,
        (const uint32_t*)kh, (const uint32_t*)kl,
        (const uint32_t*)vth, (const uint32_t*)vtl,
        (uint32_t*)oh, (uint32_t*)ol);

    gemm_bf16<<<gg, 256, gemm_smem>>>(oh, ol, woh, wol, out, nullptr, nullptr, 0, 1.0f);
}

// round 12
// speedup vs baseline: 3.1664x; 1.0074x over previous
#include <cuda_runtime.h>
#include <cuda_bf16.h>
#include <math.h>
#include <stdint.h>

// Problem constants
#define BB 2
#define LL 2048
#define DD 1024
#define HH 16
#define DH 64
#define M1 1048576
#define M4 4194304

// One big scratch buffer (bf16). Element offsets:
//  xh 0, xl 4M1, wqkvh 8M1 (3M1: Wq^T|Wk^T|Wv^T rows), wqkvl 11M1 (3M1),
//  woh 14M1, wol 15M1, qh 16M1, ql 20M1, kh 24M1, kl 28M1,
//  vth 32M1, vtl 36M1, oh 40M1, ol 44M1
__device__ __nv_bfloat16 g_buf[48 * M1];

// ---------------------------------------------------------------------------
// Helpers
// ---------------------------------------------------------------------------
__device__ __forceinline__ uint32_t s2u(const void* p) {
    return (uint32_t)__cvta_generic_to_shared(p);
}

__device__ __forceinline__ void mma_bf16(float* c, const uint32_t* a, const uint32_t* b) {
    asm volatile(
        "mma.sync.aligned.m16n8k16.row.col.f32.bf16.bf16.f32 "
        "{%0,%1,%2,%3}, {%4,%5,%6,%7}, {%8,%9}, {%0,%1,%2,%3};\n"
        : "+f"(c[0]), "+f"(c[1]), "+f"(c[2]), "+f"(c[3])
        : "r"(a[0]), "r"(a[1]), "r"(a[2]), "r"(a[3]), "r"(b[0]), "r"(b[1]));
}

__device__ __forceinline__ void mma3(float* c, const uint32_t* ah, const uint32_t* al,
                                     const uint32_t* bh, const uint32_t* bl) {
    mma_bf16(c, al, bh);
    mma_bf16(c, ah, bl);
    mma_bf16(c, ah, bh);
}

__device__ __forceinline__ void ldsm4(uint32_t& r0, uint32_t& r1, uint32_t& r2, uint32_t& r3,
                                      uint32_t addr) {
    asm volatile("ldmatrix.sync.aligned.m8n8.x4.shared.b16 {%0,%1,%2,%3}, [%4];\n"
                 : "=r"(r0), "=r"(r1), "=r"(r2), "=r"(r3) : "r"(addr));
}

__device__ __forceinline__ uint32_t packsplit(float x0, float x1, uint32_t& lo_out) {
    __nv_bfloat16 h0 = __float2bfloat16_rn(x0);
    __nv_bfloat16 h1 = __float2bfloat16_rn(x1);
    __nv_bfloat16 l0 = __float2bfloat16_rn(x0 - __bfloat162float(h0));
    __nv_bfloat16 l1 = __float2bfloat16_rn(x1 - __bfloat162float(h1));
    __nv_bfloat162 hp = __halves2bfloat162(h0, h1);
    __nv_bfloat162 lp = __halves2bfloat162(l0, l1);
    lo_out = *(uint32_t*)&lp;
    return *(uint32_t*)&hp;
}

__device__ __forceinline__ void cp_async16(uint32_t dst, const void* src) {
    asm volatile("cp.async.ca.shared.global [%0], [%1], 16;\n" :: "r"(dst), "l"(src));
}
__device__ __forceinline__ void cp_async16cg(uint32_t dst, const void* src) {
    asm volatile("cp.async.cg.shared.global [%0], [%1], 16;\n" :: "r"(dst), "l"(src));
}
__device__ __forceinline__ void cp_commit() {
    asm volatile("cp.async.commit_group;\n");
}
__device__ __forceinline__ void cp_wait0() {
    asm volatile("cp.async.wait_group 0;\n" ::: "memory");
}

// ---------------------------------------------------------------------------
// Prepass: elementwise fp32 -> bf16 hi/lo split
// ---------------------------------------------------------------------------
__global__ __launch_bounds__(256) void split_kernel(
    const float* __restrict__ in, __nv_bfloat16* __restrict__ hi,
    __nv_bfloat16* __restrict__ lo, int n)
{
    int i = blockIdx.x * 256 + threadIdx.x;
    if (i >= n) return;
    float x = in[i];
    __nv_bfloat16 h = __float2bfloat16_rn(x);
    hi[i] = h;
    lo[i] = __float2bfloat16_rn(x - __bfloat162float(h));
}

// ---------------------------------------------------------------------------
// Prepass: W [1024 in][1024 out] fp32 -> Wt [out][in] bf16 hi/lo
// ---------------------------------------------------------------------------
__global__ __launch_bounds__(256) void wtrans_kernel(
    const float* __restrict__ W, __nv_bfloat16* __restrict__ th,
    __nv_bfloat16* __restrict__ tl)
{
    __shared__ float t[32][33];
    const int tx = threadIdx.x, ty = threadIdx.y;   // 32 x 8
    const int bx = blockIdx.x * 32, by = blockIdx.y * 32;
#pragma unroll
    for (int j = 0; j < 32; j += 8)
        t[ty + j][tx] = W[(size_t)(by + ty + j) * DD + bx + tx];
    __syncthreads();
#pragma unroll
    for (int j = 0; j < 32; j += 8) {
        float x = t[tx][ty + j];
        __nv_bfloat16 h = __float2bfloat16_rn(x);
        size_t o = (size_t)(bx + ty + j) * DD + by + tx;
        th[o] = h;
        tl[o] = __float2bfloat16_rn(x - __bfloat162float(h));
    }
}

// ---------------------------------------------------------------------------
// bf16x3 GEMM: C[4096,N] = A @ Wt^T.  A hi/lo [4096][1024], Wt hi/lo [N][1024].
// 128x128 block, K-stage 32, 8 warps (2m x 4n), warp tile 64x32, ldmatrix.
// Epilogue: mode 0 = fp32 C out; mode 3 = fused QKV routing by column region
//   (cols 0-1023 -> Q split *0.125; 1024-2047 -> K split; 2048-3071 -> V
//    split + per-head transpose). For mode 3, Ch/Cl point at qh/ql; K and V
//    destinations are at fixed offsets from them.
// ---------------------------------------------------------------------------
#define GST 20
__global__ __launch_bounds__(256) void gemm_bf16(
    const __nv_bfloat16* __restrict__ Ah_g, const __nv_bfloat16* __restrict__ Al_g,
    const __nv_bfloat16* __restrict__ Bh_g, const __nv_bfloat16* __restrict__ Bl_g,
    float* __restrict__ Cf, __nv_bfloat16* __restrict__ Ch, __nv_bfloat16* __restrict__ Cl,
    int mode)
{
    extern __shared__ uint32_t sg[];
    uint32_t* Ahs = sg;               // 2 stages x 128*GST
    uint32_t* Als = sg + 5120;
    uint32_t* Bhs = sg + 10240;
    uint32_t* Bls = sg + 15360;

    const int tid = threadIdx.x;
    const int lane = tid & 31;
    const int wid = tid >> 5;
    const int warp_m = wid & 1;
    const int warp_n = wid >> 1;
    const int lq = lane >> 2;
    const int lr = lane & 3;
    const int l8 = lane & 7, lb3 = (lane >> 3) & 1, lb4 = lane >> 4;

    const int bm = blockIdx.y * 128;
    const int bn = blockIdx.x * 128;

    const uint32_t* Ah4 = (const uint32_t*)Ah_g;
    const uint32_t* Al4 = (const uint32_t*)Al_g;
    const uint32_t* Bh4 = (const uint32_t*)Bh_g;
    const uint32_t* Bl4 = (const uint32_t*)Bl_g;

    float acc[4][4][4];
#pragma unroll
    for (int mi = 0; mi < 4; mi++)
#pragma unroll
        for (int ni = 0; ni < 4; ni++)
#pragma unroll
            for (int q = 0; q < 4; q++) acc[mi][ni][q] = 0.0f;

    const uint32_t sAh = s2u(Ahs), sAl = s2u(Als), sBh = s2u(Bhs), sBl = s2u(Bls);

    const uint32_t a_off = (uint32_t)((warp_m * 64 + l8 + lb3 * 8) * GST + lb4 * 4);
    const uint32_t b_off = (uint32_t)((warp_n * 32 + l8 + lb4 * 8) * GST + lb3 * 4);

    auto load = [&](int buf, int k0u) {
#pragma unroll
        for (int j = 0; j < 2; j++) {
            int c = tid + j * 256;
            int r = c >> 2, q = (c & 3) * 4;
            uint32_t o = (uint32_t)(buf * 2560 + r * GST + q) * 4;
            size_t ao = (size_t)(bm + r) * 512 + k0u + q;
            size_t bo = (size_t)(bn + r) * 512 + k0u + q;
            cp_async16(sAh + o, Ah4 + ao);
            cp_async16(sAl + o, Al4 + ao);
            cp_async16(sBh + o, Bh4 + bo);
            cp_async16(sBl + o, Bl4 + bo);
        }
        cp_commit();
    };

    load(0, 0);
    const int T = DD / 32;

    for (int t = 0; t < T; t++) {
        cp_wait0();
        __syncthreads();
        if (t + 1 < T) load((t + 1) & 1, (t + 1) * 16);

        const uint32_t stg = (uint32_t)(t & 1) * 2560 * 4;

#pragma unroll
        for (int kk = 0; kk < 2; kk++) {
            const uint32_t kb8 = kk * 8 * 4;
            uint32_t ah[4][4], al[4][4];
#pragma unroll
            for (int mi = 0; mi < 4; mi++) {
                uint32_t ad = stg + (a_off + mi * 16 * GST) * 4 + kb8;
                ldsm4(ah[mi][0], ah[mi][1], ah[mi][2], ah[mi][3], sAh + ad);
                ldsm4(al[mi][0], al[mi][1], al[mi][2], al[mi][3], sAl + ad);
            }
#pragma unroll
            for (int p = 0; p < 2; p++) {
                uint32_t bh[4], bl[4];
                uint32_t bd = stg + (b_off + p * 16 * GST) * 4 + kb8;
                ldsm4(bh[0], bh[1], bh[2], bh[3], sBh + bd);
                ldsm4(bl[0], bl[1], bl[2], bl[3], sBl + bd);
#pragma unroll
                for (int mi = 0; mi < 4; mi++) {
                    mma3(acc[mi][2 * p],     ah[mi], al[mi], &bh[0], &bl[0]);
                    mma3(acc[mi][2 * p + 1], ah[mi], al[mi], &bh[2], &bl[2]);
                }
            }
        }
        __syncthreads();
    }

    // ---- epilogue ----
    if (mode == 0) {
#pragma unroll
        for (int mi = 0; mi < 4; mi++)
#pragma unroll
            for (int ni = 0; ni < 4; ni++) {
                int r = bm + warp_m * 64 + mi * 16 + lq;
                int cc = bn + warp_n * 32 + ni * 8 + lr * 2;
                *(float2*)&Cf[(size_t)r * DD + cc] = make_float2(acc[mi][ni][0], acc[mi][ni][1]);
                *(float2*)&Cf[(size_t)(r + 8) * DD + cc] = make_float2(acc[mi][ni][2], acc[mi][ni][3]);
            }
    } else {
        // fused QKV routing
        uint32_t* QhU = (uint32_t*)Ch;
        uint32_t* QlU = (uint32_t*)Cl;
        uint32_t* KhU = (uint32_t*)(Ch + 8 * (size_t)M1);
        uint32_t* KlU = (uint32_t*)(Cl + 8 * (size_t)M1);
        __nv_bfloat16* Vth = Ch + 16 * (size_t)M1;
        __nv_bfloat16* Vtl = Cl + 16 * (size_t)M1;
#pragma unroll
        for (int mi = 0; mi < 4; mi++)
#pragma unroll
            for (int ni = 0; ni < 4; ni++) {
                int r = bm + warp_m * 64 + mi * 16 + lq;
                int cc = bn + warp_n * 32 + ni * 8 + lr * 2;
                int region = cc >> 10, lc = cc & 1023;
                if (region == 0) {
                    uint32_t lo, hi;
                    hi = packsplit(acc[mi][ni][0] * 0.125f, acc[mi][ni][1] * 0.125f, lo);
                    QhU[(size_t)r * 512 + (lc >> 1)] = hi;
                    QlU[(size_t)r * 512 + (lc >> 1)] = lo;
                    hi = packsplit(acc[mi][ni][2] * 0.125f, acc[mi][ni][3] * 0.125f, lo);
                    QhU[(size_t)(r + 8) * 512 + (lc >> 1)] = hi;
                    QlU[(size_t)(r + 8) * 512 + (lc >> 1)] = lo;
                } else if (region == 1) {
                    uint32_t lo, hi;
                    hi = packsplit(acc[mi][ni][0], acc[mi][ni][1], lo);
                    KhU[(size_t)r * 512 + (lc >> 1)] = hi;
                    KlU[(size_t)r * 512 + (lc >> 1)] = lo;
                    hi = packsplit(acc[mi][ni][2], acc[mi][ni][3], lo);
                    KhU[(size_t)(r + 8) * 512 + (lc >> 1)] = hi;
                    KlU[(size_t)(r + 8) * 512 + (lc >> 1)] = lo;
                } else {
#pragma unroll
                    for (int q = 0; q < 4; q++) {
                        int rr = r + (q >> 1) * 8;
                        int ccl = lc + (q & 1);
                        int hh = ccl >> 6, e = ccl & 63, bI = rr >> 11, ltok = rr & 2047;
                        size_t dst = (((size_t)bI * HH + hh) * DH + e) * LL + ltok;
                        float x = acc[mi][ni][q];
                        __nv_bfloat16 hv = __float2bfloat16_rn(x);
                        Vth[dst] = hv;
                        Vtl[dst] = __float2bfloat16_rn(x - __bfloat162float(hv));
                    }
                }
            }
    }
}

// ---------------------------------------------------------------------------
// bf16x3 flash attention, causal. 256 threads (8 warps), BQ=128, BKV=64.
// Warp w owns q rows [16w, 16w+16): 1 m16 frag x 8 n8 frags. P in registers.
// K/V double-buffered cp.async (.cg). qt reversed (heavy tiles first).
// ---------------------------------------------------------------------------
#define AS 36
__global__ __launch_bounds__(256) void attn_bf16(
    const uint32_t* __restrict__ Qh_g, const uint32_t* __restrict__ Ql_g,
    const uint32_t* __restrict__ Kh_g, const uint32_t* __restrict__ Kl_g,
    const uint32_t* __restrict__ Vh_g, const uint32_t* __restrict__ Vl_g,
    uint32_t* __restrict__ Oh_g, uint32_t* __restrict__ Ol_g)
{
    extern __shared__ uint32_t sm[];
    uint32_t* Qh = sm;               // 128*AS = 4608
    uint32_t* Ql = Qh + 4608;
    uint32_t* KV = Ql + 4608;        // 2 stages x [Kh|Kl|Vh|Vl] x 2304

    const int tid = threadIdx.x;
    const int lane = tid & 31;
    const int w = tid >> 5;          // 0..7
    const int lq = lane >> 2;
    const int lr = lane & 3;
    const int l8 = lane & 7, lb3 = (lane >> 3) & 1, lb4 = lane >> 4;

    const int qt = (int)(gridDim.x - 1) - (int)blockIdx.x;
    const int h  = blockIdx.y;
    const int b  = blockIdx.z;
    const int qb = qt * 128;

    const uint32_t sQh = s2u(Qh), sQl = s2u(Ql), sKV = s2u(KV);

    const uint32_t q_off = (uint32_t)((w * 16 + l8 + lb3 * 8) * AS + lb4 * 4);
    const uint32_t kv_off = (uint32_t)((l8 + lb4 * 8) * AS + lb3 * 4);

    // ---- issue Q loads (1024 16B-chunks, 4 per thread) ----
#pragma unroll
    for (int j = 0; j < 4; j++) {
        int idx = tid + j * 256;
        int r = idx >> 3, cq = (idx & 7) * 4;
        size_t g = (size_t)(b * LL + qb + r) * 512 + h * 32 + cq;
        uint32_t o = (uint32_t)(r * AS + cq) * 4;
        cp_async16(sQh + o, Qh_g + g);
        cp_async16(sQl + o, Ql_g + g);
    }
    cp_commit();

    auto load_kv = [&](int buf, int kb) {
        uint32_t base = sKV + (uint32_t)buf * 9216 * 4;
#pragma unroll
        for (int j = 0; j < 2; j++) {
            int idx = tid + j * 256;
            int r = idx >> 3, cq = (idx & 7) * 4;
            uint32_t o = (uint32_t)(r * AS + cq) * 4;
            size_t gk = (size_t)(b * LL + kb + r) * 512 + h * 32 + cq;
            cp_async16cg(base + o,            Kh_g + gk);
            cp_async16cg(base + 2304 * 4 + o, Kl_g + gk);
            size_t gv = ((size_t)(b * HH + h) * DH + r) * 1024 + (kb >> 1) + cq;
            cp_async16cg(base + 4608 * 4 + o, Vh_g + gv);
            cp_async16cg(base + 6912 * 4 + o, Vl_g + gv);
        }
        cp_commit();
    };

    load_kv(0, 0);

    float oacc[8][4];
    float m[2], l[2];
    m[0] = m[1] = -1e30f;
    l[0] = l[1] = 0.0f;
#pragma unroll
    for (int ni = 0; ni < 8; ni++)
#pragma unroll
        for (int q = 0; q < 4; q++) oacc[ni][q] = 0.0f;

    const int ntiles = 2 * qt + 2;
    for (int kt = 0; kt < ntiles; kt++) {
        const int kb = kt * 64;
        cp_wait0();
        __syncthreads();
        if (kt + 1 < ntiles) load_kv((kt + 1) & 1, (kt + 1) * 64);

        const uint32_t kvb = sKV + (uint32_t)(kt & 1) * 9216 * 4;
        const uint32_t sKh = kvb, sKl = kvb + 2304 * 4;
        const uint32_t sVh = kvb + 4608 * 4, sVl = kvb + 6912 * 4;

        // --- S = Q @ K^T ---
        float sacc[8][4];
#pragma unroll
        for (int ni = 0; ni < 8; ni++)
#pragma unroll
            for (int q = 0; q < 4; q++) sacc[ni][q] = 0.0f;

#pragma unroll
        for (int kk = 0; kk < 4; kk++) {
            const uint32_t kb8 = kk * 8 * 4;
            uint32_t ah[4], al[4];
            uint32_t ad = q_off * 4 + kb8;
            ldsm4(ah[0], ah[1], ah[2], ah[3], sQh + ad);
            ldsm4(al[0], al[1], al[2], al[3], sQl + ad);
#pragma unroll
            for (int p = 0; p < 4; p++) {
                uint32_t bh[4], bl[4];
                uint32_t bd = (kv_off + p * 16 * AS) * 4 + kb8;
                ldsm4(bh[0], bh[1], bh[2], bh[3], sKh + bd);
                ldsm4(bl[0], bl[1], bl[2], bl[3], sKl + bd);
                mma3(sacc[2 * p],     ah, al, &bh[0], &bl[0]);
                mma3(sacc[2 * p + 1], ah, al, &bh[2], &bl[2]);
            }
        }

        // --- causal mask ---
        if (kb + 63 > qb) {
#pragma unroll
            for (int ni = 0; ni < 8; ni++)
#pragma unroll
                for (int q = 0; q < 4; q++) {
                    int row_g = qb + w * 16 + lq + (q >> 1) * 8;
                    int col_g = kb + ni * 8 + lr * 2 + (q & 1);
                    if (col_g > row_g) sacc[ni][q] = -1e30f;
                }
        }

        // --- online softmax (rows j=0: lq; j=1: lq+8) ---
        float rmax[2] = {-1e30f, -1e30f};
#pragma unroll
        for (int ni = 0; ni < 8; ni++)
#pragma unroll
            for (int q = 0; q < 4; q++)
                rmax[q >> 1] = fmaxf(rmax[q >> 1], sacc[ni][q]);
#pragma unroll
        for (int j = 0; j < 2; j++) {
            rmax[j] = fmaxf(rmax[j], __shfl_xor_sync(0xffffffffu, rmax[j], 1));
            rmax[j] = fmaxf(rmax[j], __shfl_xor_sync(0xffffffffu, rmax[j], 2));
        }

        float sc[2], rs[2];
#pragma unroll
        for (int j = 0; j < 2; j++) {
            float mn = fmaxf(m[j], rmax[j]);
            sc[j] = __expf(m[j] - mn);
            m[j] = mn;
            rs[j] = 0.0f;
        }
#pragma unroll
        for (int ni = 0; ni < 8; ni++)
#pragma unroll
            for (int q = 0; q < 4; q++) {
                float p = __expf(sacc[ni][q] - m[q >> 1]);
                sacc[ni][q] = p;
                rs[q >> 1] += p;
            }
#pragma unroll
        for (int j = 0; j < 2; j++) {
            rs[j] += __shfl_xor_sync(0xffffffffu, rs[j], 1);
            rs[j] += __shfl_xor_sync(0xffffffffu, rs[j], 2);
            l[j] = l[j] * sc[j] + rs[j];
        }
#pragma unroll
        for (int ni = 0; ni < 8; ni++)
#pragma unroll
            for (int q = 0; q < 4; q++)
                oacc[ni][q] *= sc[q >> 1];

        // --- O += P @ V, P fragments formed in registers ---
#pragma unroll
        for (int kk = 0; kk < 4; kk++) {
            uint32_t ph[4], pl[4];
            ph[0] = packsplit(sacc[2 * kk][0],     sacc[2 * kk][1],     pl[0]);
            ph[1] = packsplit(sacc[2 * kk][2],     sacc[2 * kk][3],     pl[1]);
            ph[2] = packsplit(sacc[2 * kk + 1][0], sacc[2 * kk + 1][1], pl[2]);
            ph[3] = packsplit(sacc[2 * kk + 1][2], sacc[2 * kk + 1][3], pl[3]);
            const uint32_t kb8 = kk * 8 * 4;
#pragma unroll
            for (int p = 0; p < 4; p++) {
                uint32_t bh[4], bl[4];
                uint32_t bd = (kv_off + p * 16 * AS) * 4 + kb8;
                ldsm4(bh[0], bh[1], bh[2], bh[3], sVh + bd);
                ldsm4(bl[0], bl[1], bl[2], bl[3], sVl + bd);
                mma3(oacc[2 * p],     ph, pl, &bh[0], &bl[0]);
                mma3(oacc[2 * p + 1], ph, pl, &bh[2], &bl[2]);
            }
        }
        __syncthreads();
    }

    // epilogue: normalize + split-store O
    float inv[2];
    inv[0] = 1.0f / l[0];
    inv[1] = 1.0f / l[1];
#pragma unroll
    for (int ni = 0; ni < 8; ni++) {
        int r = w * 16 + lq;
        int cu = ni * 4 + lr;
        size_t g0 = (size_t)(b * LL + qb + r) * 512 + h * 32 + cu;
        size_t g1 = (size_t)(b * LL + qb + r + 8) * 512 + h * 32 + cu;
        uint32_t lo, hi;
        hi = packsplit(oacc[ni][0] * inv[0], oacc[ni][1] * inv[0], lo);
        Oh_g[g0] = hi; Ol_g[g0] = lo;
        hi = packsplit(oacc[ni][2] * inv[1], oacc[ni][3] * inv[1], lo);
        Oh_g[g1] = hi; Ol_g[g1] = lo;
    }
}

// ---------------------------------------------------------------------------
extern "C" void kernel_launch(void* const* d_in, const int* in_sizes, int n_in,
                              void* d_out, int out_size)
{
    (void)in_sizes; (void)n_in; (void)out_size;
    const float* x    = (const float*)d_in[0];
    const float* Wq   = (const float*)d_in[1];
    const float* Wk   = (const float*)d_in[2];
    const float* Wv   = (const float*)d_in[3];
    const float* Wout = (const float*)d_in[4];
    float* out = (float*)d_out;

    __nv_bfloat16* g;
    cudaGetSymbolAddress((void**)&g, g_buf);

    __nv_bfloat16* xh    = g;
    __nv_bfloat16* xl    = g + M4;
    __nv_bfloat16* wqkvh = g + 8 * (size_t)M1;    // [3072][1024]
    __nv_bfloat16* wqkvl = g + 11 * (size_t)M1;
    __nv_bfloat16* woh   = g + 14 * (size_t)M1;
    __nv_bfloat16* wol   = g + 15 * (size_t)M1;
    __nv_bfloat16* qh    = g + 16 * (size_t)M1;
    __nv_bfloat16* ql    = g + 20 * (size_t)M1;
    __nv_bfloat16* kh    = g + 24 * (size_t)M1;
    __nv_bfloat16* kl    = g + 28 * (size_t)M1;
    __nv_bfloat16* vth   = g + 32 * (size_t)M1;
    __nv_bfloat16* vtl   = g + 36 * (size_t)M1;
    __nv_bfloat16* oh    = g + 40 * (size_t)M1;
    __nv_bfloat16* ol    = g + 44 * (size_t)M1;

    // Prepasses
    split_kernel<<<M4 / 256, 256>>>(x, xh, xl, M4);
    dim3 wtb(32, 8), wtg(32, 32);
    wtrans_kernel<<<wtg, wtb>>>(Wq, wqkvh,                wqkvl);
    wtrans_kernel<<<wtg, wtb>>>(Wk, wqkvh + (size_t)M1,   wqkvl + (size_t)M1);
    wtrans_kernel<<<wtg, wtb>>>(Wv, wqkvh + 2 * (size_t)M1, wqkvl + 2 * (size_t)M1);
    wtrans_kernel<<<wtg, wtb>>>(Wout, woh, wol);

    const int gemm_smem = 20480 * 4;
    cudaFuncSetAttribute(gemm_bf16, cudaFuncAttributeMaxDynamicSharedMemorySize, gemm_smem);

    // Fused QKV GEMM: N=3072
    dim3 gqkv(3072 / 128, (BB * LL) / 128);   // 24 x 32 = 768 CTAs
    gemm_bf16<<<gqkv, 256, gemm_smem>>>(xh, xl, wqkvh, wqkvl, nullptr, qh, ql, 3);

    const int attn_smem = (4608 * 2 + 9216 * 2) * 4;   // 110592 B
    cudaFuncSetAttribute(attn_bf16, cudaFuncAttributeMaxDynamicSharedMemorySize, attn_smem);
    dim3 ga(LL / 128, HH, BB);
    attn_bf16<<<ga, 256, attn_smem>>>(
        (const uint32_t*)qh, (const uint32_t*)ql,
        (const uint32_t*)kh, (const uint32_t*)kl,
        (const uint32_t*)vth, (const uint32_t*)vtl,
        (uint32_t*)oh, (uint32_t*)ol);

    // Output projection: N=1024
    dim3 go(DD / 128, (BB * LL) / 128);       // 8 x 32
    gemm_bf16<<<go, 256, gemm_smem>>>(oh, ol, woh, wol, out, nullptr, nullptr, 0);
}

// round 13
// speedup vs baseline: 3.5652x; 1.1260x over previous
#include <cuda_runtime.h>
#include <cuda_bf16.h>
#include <cuda_fp16.h>
#include <math.h>
#include <stdint.h>

// Problem constants
#define BB 2
#define LL 2048
#define DD 1024
#define HH 16
#define DH 64
#define M1 1048576
#define M4 4194304

// One big scratch buffer (16-bit slots). Element offsets:
//  xh 0, xl 4M1, wqkvh 8M1 (3M1), wqkvl 11M1 (3M1), woh 14M1, wol 15M1,
//  qh 16M1 (fp16), ql 20M1 (fp16), kh 24M1 (fp16, single), vth 32M1 (fp16,
//  single, per-head transposed), oh 40M1 (bf16 hi), ol 44M1 (bf16 lo)
__device__ __nv_bfloat16 g_buf[48 * M1];

// ---------------------------------------------------------------------------
// Helpers
// ---------------------------------------------------------------------------
__device__ __forceinline__ uint32_t s2u(const void* p) {
    return (uint32_t)__cvta_generic_to_shared(p);
}

__device__ __forceinline__ void mma_bf16(float* c, const uint32_t* a, const uint32_t* b) {
    asm volatile(
        "mma.sync.aligned.m16n8k16.row.col.f32.bf16.bf16.f32 "
        "{%0,%1,%2,%3}, {%4,%5,%6,%7}, {%8,%9}, {%0,%1,%2,%3};\n"
        : "+f"(c[0]), "+f"(c[1]), "+f"(c[2]), "+f"(c[3])
        : "r"(a[0]), "r"(a[1]), "r"(a[2]), "r"(a[3]), "r"(b[0]), "r"(b[1]));
}

__device__ __forceinline__ void mma_f16(float* c, const uint32_t* a, const uint32_t* b) {
    asm volatile(
        "mma.sync.aligned.m16n8k16.row.col.f32.f16.f16.f32 "
        "{%0,%1,%2,%3}, {%4,%5,%6,%7}, {%8,%9}, {%0,%1,%2,%3};\n"
        : "+f"(c[0]), "+f"(c[1]), "+f"(c[2]), "+f"(c[3])
        : "r"(a[0]), "r"(a[1]), "r"(a[2]), "r"(a[3]), "r"(b[0]), "r"(b[1]));
}

__device__ __forceinline__ void mma3(float* c, const uint32_t* ah, const uint32_t* al,
                                     const uint32_t* bh, const uint32_t* bl) {
    mma_bf16(c, al, bh);
    mma_bf16(c, ah, bl);
    mma_bf16(c, ah, bh);
}

__device__ __forceinline__ void ldsm4(uint32_t& r0, uint32_t& r1, uint32_t& r2, uint32_t& r3,
                                      uint32_t addr) {
    asm volatile("ldmatrix.sync.aligned.m8n8.x4.shared.b16 {%0,%1,%2,%3}, [%4];\n"
                 : "=r"(r0), "=r"(r1), "=r"(r2), "=r"(r3) : "r"(addr));
}

// bf16 split (pair) -> packed hi (return), lo (out)
__device__ __forceinline__ uint32_t packsplit(float x0, float x1, uint32_t& lo_out) {
    __nv_bfloat16 h0 = __float2bfloat16_rn(x0);
    __nv_bfloat16 h1 = __float2bfloat16_rn(x1);
    __nv_bfloat16 l0 = __float2bfloat16_rn(x0 - __bfloat162float(h0));
    __nv_bfloat16 l1 = __float2bfloat16_rn(x1 - __bfloat162float(h1));
    __nv_bfloat162 hp = __halves2bfloat162(h0, h1);
    __nv_bfloat162 lp = __halves2bfloat162(l0, l1);
    lo_out = *(uint32_t*)&lp;
    return *(uint32_t*)&hp;
}

// fp16 split (pair) -> packed hi (return), lo (out)
__device__ __forceinline__ uint32_t packsplit_h(float x0, float x1, uint32_t& lo_out) {
    __half h0 = __float2half_rn(x0);
    __half h1 = __float2half_rn(x1);
    __half l0 = __float2half_rn(x0 - __half2float(h0));
    __half l1 = __float2half_rn(x1 - __half2float(h1));
    __half2 hp = __halves2half2(h0, h1);
    __half2 lp = __halves2half2(l0, l1);
    lo_out = *(uint32_t*)&lp;
    return *(uint32_t*)&hp;
}

__device__ __forceinline__ uint32_t packh(float x0, float x1) {
    __half2 hp = __floats2half2_rn(x0, x1);
    return *(uint32_t*)&hp;
}

__device__ __forceinline__ void cp_async16(uint32_t dst, const void* src) {
    asm volatile("cp.async.ca.shared.global [%0], [%1], 16;\n" :: "r"(dst), "l"(src));
}
__device__ __forceinline__ void cp_async16cg(uint32_t dst, const void* src) {
    asm volatile("cp.async.cg.shared.global [%0], [%1], 16;\n" :: "r"(dst), "l"(src));
}
__device__ __forceinline__ void cp_commit() {
    asm volatile("cp.async.commit_group;\n");
}
__device__ __forceinline__ void cp_wait0() {
    asm volatile("cp.async.wait_group 0;\n" ::: "memory");
}

// ---------------------------------------------------------------------------
// Prepass: elementwise fp32 -> bf16 hi/lo split (x)
// ---------------------------------------------------------------------------
__global__ __launch_bounds__(256) void split_kernel(
    const float* __restrict__ in, __nv_bfloat16* __restrict__ hi,
    __nv_bfloat16* __restrict__ lo, int n)
{
    int i = blockIdx.x * 256 + threadIdx.x;
    if (i >= n) return;
    float x = in[i];
    __nv_bfloat16 h = __float2bfloat16_rn(x);
    hi[i] = h;
    lo[i] = __float2bfloat16_rn(x - __bfloat162float(h));
}

// ---------------------------------------------------------------------------
// Prepass: 4 weights [1024][1024] fp32 -> transposed bf16 hi/lo, one launch
// ---------------------------------------------------------------------------
struct WT4 {
    const float* s[4];
    __nv_bfloat16* h[4];
    __nv_bfloat16* l[4];
};
__global__ __launch_bounds__(256) void wtrans4_kernel(WT4 wt)
{
    __shared__ float t[32][33];
    const int z = blockIdx.z;
    const float* W = wt.s[z];
    __nv_bfloat16* th = wt.h[z];
    __nv_bfloat16* tl = wt.l[z];
    const int tx = threadIdx.x, ty = threadIdx.y;   // 32 x 8
    const int bx = blockIdx.x * 32, by = blockIdx.y * 32;
#pragma unroll
    for (int j = 0; j < 32; j += 8)
        t[ty + j][tx] = W[(size_t)(by + ty + j) * DD + bx + tx];
    __syncthreads();
#pragma unroll
    for (int j = 0; j < 32; j += 8) {
        float x = t[tx][ty + j];
        __nv_bfloat16 h = __float2bfloat16_rn(x);
        size_t o = (size_t)(bx + ty + j) * DD + by + tx;
        th[o] = h;
        tl[o] = __float2bfloat16_rn(x - __bfloat162float(h));
    }
}

// ---------------------------------------------------------------------------
// bf16x3 GEMM: C[4096,N] = A @ Wt^T.  128x128 block, 8 warps, ldmatrix.
// mode 0: fp32 C out.  mode 3: fused QKV routing:
//   cols 0-1023  -> Q fp16 hi/lo split (qh/ql)
//   1024-2047    -> K fp16 single (kh)
//   2048-3071    -> V fp16 single, per-head transposed (vth)
// ---------------------------------------------------------------------------
#define GST 20
__global__ __launch_bounds__(256) void gemm_bf16(
    const __nv_bfloat16* __restrict__ Ah_g, const __nv_bfloat16* __restrict__ Al_g,
    const __nv_bfloat16* __restrict__ Bh_g, const __nv_bfloat16* __restrict__ Bl_g,
    float* __restrict__ Cf, __nv_bfloat16* __restrict__ Ch, __nv_bfloat16* __restrict__ Cl,
    int mode)
{
    extern __shared__ uint32_t sg[];
    uint32_t* Ahs = sg;
    uint32_t* Als = sg + 5120;
    uint32_t* Bhs = sg + 10240;
    uint32_t* Bls = sg + 15360;

    const int tid = threadIdx.x;
    const int lane = tid & 31;
    const int wid = tid >> 5;
    const int warp_m = wid & 1;
    const int warp_n = wid >> 1;
    const int lq = lane >> 2;
    const int lr = lane & 3;
    const int l8 = lane & 7, lb3 = (lane >> 3) & 1, lb4 = lane >> 4;

    const int bm = blockIdx.y * 128;
    const int bn = blockIdx.x * 128;

    const uint32_t* Ah4 = (const uint32_t*)Ah_g;
    const uint32_t* Al4 = (const uint32_t*)Al_g;
    const uint32_t* Bh4 = (const uint32_t*)Bh_g;
    const uint32_t* Bl4 = (const uint32_t*)Bl_g;

    float acc[4][4][4];
#pragma unroll
    for (int mi = 0; mi < 4; mi++)
#pragma unroll
        for (int ni = 0; ni < 4; ni++)
#pragma unroll
            for (int q = 0; q < 4; q++) acc[mi][ni][q] = 0.0f;

    const uint32_t sAh = s2u(Ahs), sAl = s2u(Als), sBh = s2u(Bhs), sBl = s2u(Bls);

    const uint32_t a_off = (uint32_t)((warp_m * 64 + l8 + lb3 * 8) * GST + lb4 * 4);
    const uint32_t b_off = (uint32_t)((warp_n * 32 + l8 + lb4 * 8) * GST + lb3 * 4);

    auto load = [&](int buf, int k0u) {
#pragma unroll
        for (int j = 0; j < 2; j++) {
            int c = tid + j * 256;
            int r = c >> 2, q = (c & 3) * 4;
            uint32_t o = (uint32_t)(buf * 2560 + r * GST + q) * 4;
            size_t ao = (size_t)(bm + r) * 512 + k0u + q;
            size_t bo = (size_t)(bn + r) * 512 + k0u + q;
            cp_async16(sAh + o, Ah4 + ao);
            cp_async16(sAl + o, Al4 + ao);
            cp_async16(sBh + o, Bh4 + bo);
            cp_async16(sBl + o, Bl4 + bo);
        }
        cp_commit();
    };

    load(0, 0);
    const int T = DD / 32;

    for (int t = 0; t < T; t++) {
        cp_wait0();
        __syncthreads();
        if (t + 1 < T) load((t + 1) & 1, (t + 1) * 16);

        const uint32_t stg = (uint32_t)(t & 1) * 2560 * 4;

#pragma unroll
        for (int kk = 0; kk < 2; kk++) {
            const uint32_t kb8 = kk * 8 * 4;
            uint32_t ah[4][4], al[4][4];
#pragma unroll
            for (int mi = 0; mi < 4; mi++) {
                uint32_t ad = stg + (a_off + mi * 16 * GST) * 4 + kb8;
                ldsm4(ah[mi][0], ah[mi][1], ah[mi][2], ah[mi][3], sAh + ad);
                ldsm4(al[mi][0], al[mi][1], al[mi][2], al[mi][3], sAl + ad);
            }
#pragma unroll
            for (int p = 0; p < 2; p++) {
                uint32_t bh[4], bl[4];
                uint32_t bd = stg + (b_off + p * 16 * GST) * 4 + kb8;
                ldsm4(bh[0], bh[1], bh[2], bh[3], sBh + bd);
                ldsm4(bl[0], bl[1], bl[2], bl[3], sBl + bd);
#pragma unroll
                for (int mi = 0; mi < 4; mi++) {
                    mma3(acc[mi][2 * p],     ah[mi], al[mi], &bh[0], &bl[0]);
                    mma3(acc[mi][2 * p + 1], ah[mi], al[mi], &bh[2], &bl[2]);
                }
            }
        }
        __syncthreads();
    }

    // ---- epilogue ----
    if (mode == 0) {
#pragma unroll
        for (int mi = 0; mi < 4; mi++)
#pragma unroll
            for (int ni = 0; ni < 4; ni++) {
                int r = bm + warp_m * 64 + mi * 16 + lq;
                int cc = bn + warp_n * 32 + ni * 8 + lr * 2;
                *(float2*)&Cf[(size_t)r * DD + cc] = make_float2(acc[mi][ni][0], acc[mi][ni][1]);
                *(float2*)&Cf[(size_t)(r + 8) * DD + cc] = make_float2(acc[mi][ni][2], acc[mi][ni][3]);
            }
    } else {
        // fused QKV routing (Ch = qh base, fp16 views at fixed offsets)
        uint32_t* QhU = (uint32_t*)Ch;
        uint32_t* QlU = (uint32_t*)Cl;
        uint32_t* KhU = (uint32_t*)(Ch + 8 * (size_t)M1);
        __half*   Vth = (__half*)(Ch + 16 * (size_t)M1);
#pragma unroll
        for (int mi = 0; mi < 4; mi++)
#pragma unroll
            for (int ni = 0; ni < 4; ni++) {
                int r = bm + warp_m * 64 + mi * 16 + lq;
                int cc = bn + warp_n * 32 + ni * 8 + lr * 2;
                int region = cc >> 10, lc = cc & 1023;
                if (region == 0) {
                    uint32_t lo, hi;
                    hi = packsplit_h(acc[mi][ni][0], acc[mi][ni][1], lo);
                    QhU[(size_t)r * 512 + (lc >> 1)] = hi;
                    QlU[(size_t)r * 512 + (lc >> 1)] = lo;
                    hi = packsplit_h(acc[mi][ni][2], acc[mi][ni][3], lo);
                    QhU[(size_t)(r + 8) * 512 + (lc >> 1)] = hi;
                    QlU[(size_t)(r + 8) * 512 + (lc >> 1)] = lo;
                } else if (region == 1) {
                    KhU[(size_t)r * 512 + (lc >> 1)] = packh(acc[mi][ni][0], acc[mi][ni][1]);
                    KhU[(size_t)(r + 8) * 512 + (lc >> 1)] = packh(acc[mi][ni][2], acc[mi][ni][3]);
                } else {
#pragma unroll
                    for (int q = 0; q < 4; q++) {
                        int rr = r + (q >> 1) * 8;
                        int ccl = lc + (q & 1);
                        int hh = ccl >> 6, e = ccl & 63, bI = rr >> 11, ltok = rr & 2047;
                        size_t dst = (((size_t)bI * HH + hh) * DH + e) * LL + ltok;
                        Vth[dst] = __float2half_rn(acc[mi][ni][q]);
                    }
                }
            }
    }
}

// ---------------------------------------------------------------------------
// fp16 2-product flash attention, causal. 256 threads (8 warps), BQ=128,
// BKV=64. Q fp16 hi/lo; K,V fp16 single (one-sided compensation).
// S scaled by 1/8 post-MMA. P in registers (fp16 split). Warp-level skip of
// fully-masked diagonal tiles. Output: bf16 hi/lo split for final GEMM.
// ---------------------------------------------------------------------------
#define AS 36
__global__ __launch_bounds__(256) void attn_f16(
    const uint32_t* __restrict__ Qh_g, const uint32_t* __restrict__ Ql_g,
    const uint32_t* __restrict__ Kh_g, const uint32_t* __restrict__ Vh_g,
    uint32_t* __restrict__ Oh_g, uint32_t* __restrict__ Ol_g)
{
    extern __shared__ uint32_t sm[];
    uint32_t* Qh = sm;               // 128*AS = 4608
    uint32_t* Ql = Qh + 4608;
    uint32_t* KV = Ql + 4608;        // 2 stages x [Kh|Vh] x 2304 = 9216

    const int tid = threadIdx.x;
    const int lane = tid & 31;
    const int w = tid >> 5;          // 0..7
    const int lq = lane >> 2;
    const int lr = lane & 3;
    const int l8 = lane & 7, lb3 = (lane >> 3) & 1, lb4 = lane >> 4;

    const int qt = (int)(gridDim.x - 1) - (int)blockIdx.x;   // heavy first
    const int h  = blockIdx.y;
    const int b  = blockIdx.z;
    const int qb = qt * 128;

    const uint32_t sQh = s2u(Qh), sQl = s2u(Ql), sKV = s2u(KV);

    const uint32_t q_off = (uint32_t)((w * 16 + l8 + lb3 * 8) * AS + lb4 * 4);
    const uint32_t kv_off = (uint32_t)((l8 + lb4 * 8) * AS + lb3 * 4);

    // ---- issue Q loads ----
#pragma unroll
    for (int j = 0; j < 4; j++) {
        int idx = tid + j * 256;
        int r = idx >> 3, cq = (idx & 7) * 4;
        size_t g = (size_t)(b * LL + qb + r) * 512 + h * 32 + cq;
        uint32_t o = (uint32_t)(r * AS + cq) * 4;
        cp_async16(sQh + o, Qh_g + g);
        cp_async16(sQl + o, Ql_g + g);
    }
    cp_commit();

    auto load_kv = [&](int buf, int kb) {
        uint32_t base = sKV + (uint32_t)buf * 4608 * 4;
#pragma unroll
        for (int j = 0; j < 2; j++) {
            int idx = tid + j * 256;
            int r = idx >> 3, cq = (idx & 7) * 4;
            uint32_t o = (uint32_t)(r * AS + cq) * 4;
            size_t gk = (size_t)(b * LL + kb + r) * 512 + h * 32 + cq;
            cp_async16cg(base + o, Kh_g + gk);
            size_t gv = ((size_t)(b * HH + h) * DH + r) * 1024 + (kb >> 1) + cq;
            cp_async16cg(base + 2304 * 4 + o, Vh_g + gv);
        }
        cp_commit();
    };

    load_kv(0, 0);

    float oacc[8][4];
    float m[2], l[2];
    m[0] = m[1] = -1e30f;
    l[0] = l[1] = 0.0f;
#pragma unroll
    for (int ni = 0; ni < 8; ni++)
#pragma unroll
        for (int q = 0; q < 4; q++) oacc[ni][q] = 0.0f;

    const int ntiles = 2 * qt + 2;
    for (int kt = 0; kt < ntiles; kt++) {
        const int kb = kt * 64;
        cp_wait0();
        __syncthreads();
        if (kt + 1 < ntiles) load_kv((kt + 1) & 1, (kt + 1) * 64);

        // warp fully above causal boundary for this tile? (rows < kb)
        const bool active = (kb <= qb + w * 16 + 15);
        if (active) {
            const uint32_t kvb = sKV + (uint32_t)(kt & 1) * 4608 * 4;
            const uint32_t sKh = kvb, sVh = kvb + 2304 * 4;

            // --- S = (Qh + Ql) @ Kh^T ---
            float sacc[8][4];
#pragma unroll
            for (int ni = 0; ni < 8; ni++)
#pragma unroll
                for (int q = 0; q < 4; q++) sacc[ni][q] = 0.0f;

#pragma unroll
            for (int kk = 0; kk < 4; kk++) {
                const uint32_t kb8 = kk * 8 * 4;
                uint32_t ah[4], al[4];
                uint32_t ad = q_off * 4 + kb8;
                ldsm4(ah[0], ah[1], ah[2], ah[3], sQh + ad);
                ldsm4(al[0], al[1], al[2], al[3], sQl + ad);
#pragma unroll
                for (int p = 0; p < 4; p++) {
                    uint32_t bh[4];
                    uint32_t bd = (kv_off + p * 16 * AS) * 4 + kb8;
                    ldsm4(bh[0], bh[1], bh[2], bh[3], sKh + bd);
                    mma_f16(sacc[2 * p],     al, &bh[0]);
                    mma_f16(sacc[2 * p],     ah, &bh[0]);
                    mma_f16(sacc[2 * p + 1], al, &bh[2]);
                    mma_f16(sacc[2 * p + 1], ah, &bh[2]);
                }
            }

            // --- scale + causal mask ---
            if (kb + 63 > qb + w * 16) {
#pragma unroll
                for (int ni = 0; ni < 8; ni++)
#pragma unroll
                    for (int q = 0; q < 4; q++) {
                        int row_g = qb + w * 16 + lq + (q >> 1) * 8;
                        int col_g = kb + ni * 8 + lr * 2 + (q & 1);
                        sacc[ni][q] = (col_g <= row_g) ? sacc[ni][q] * 0.125f : -1e30f;
                    }
            } else {
#pragma unroll
                for (int ni = 0; ni < 8; ni++)
#pragma unroll
                    for (int q = 0; q < 4; q++) sacc[ni][q] *= 0.125f;
            }

            // --- online softmax ---
            float rmax[2] = {-1e30f, -1e30f};
#pragma unroll
            for (int ni = 0; ni < 8; ni++)
#pragma unroll
                for (int q = 0; q < 4; q++)
                    rmax[q >> 1] = fmaxf(rmax[q >> 1], sacc[ni][q]);
#pragma unroll
            for (int j = 0; j < 2; j++) {
                rmax[j] = fmaxf(rmax[j], __shfl_xor_sync(0xffffffffu, rmax[j], 1));
                rmax[j] = fmaxf(rmax[j], __shfl_xor_sync(0xffffffffu, rmax[j], 2));
            }

            float sc[2], rs[2];
#pragma unroll
            for (int j = 0; j < 2; j++) {
                float mn = fmaxf(m[j], rmax[j]);
                sc[j] = __expf(m[j] - mn);
                m[j] = mn;
                rs[j] = 0.0f;
            }
#pragma unroll
            for (int ni = 0; ni < 8; ni++)
#pragma unroll
                for (int q = 0; q < 4; q++) {
                    float p = __expf(sacc[ni][q] - m[q >> 1]);
                    sacc[ni][q] = p;
                    rs[q >> 1] += p;
                }
#pragma unroll
            for (int j = 0; j < 2; j++) {
                rs[j] += __shfl_xor_sync(0xffffffffu, rs[j], 1);
                rs[j] += __shfl_xor_sync(0xffffffffu, rs[j], 2);
                l[j] = l[j] * sc[j] + rs[j];
            }
#pragma unroll
            for (int ni = 0; ni < 8; ni++)
#pragma unroll
                for (int q = 0; q < 4; q++)
                    oacc[ni][q] *= sc[q >> 1];

            // --- O += (Ph + Pl) @ Vh ---
#pragma unroll
            for (int kk = 0; kk < 4; kk++) {
                uint32_t ph[4], pl[4];
                ph[0] = packsplit_h(sacc[2 * kk][0],     sacc[2 * kk][1],     pl[0]);
                ph[1] = packsplit_h(sacc[2 * kk][2],     sacc[2 * kk][3],     pl[1]);
                ph[2] = packsplit_h(sacc[2 * kk + 1][0], sacc[2 * kk + 1][1], pl[2]);
                ph[3] = packsplit_h(sacc[2 * kk + 1][2], sacc[2 * kk + 1][3], pl[3]);
                const uint32_t kb8 = kk * 8 * 4;
#pragma unroll
                for (int p = 0; p < 4; p++) {
                    uint32_t bh[4];
                    uint32_t bd = (kv_off + p * 16 * AS) * 4 + kb8;
                    ldsm4(bh[0], bh[1], bh[2], bh[3], sVh + bd);
                    mma_f16(oacc[2 * p],     pl, &bh[0]);
                    mma_f16(oacc[2 * p],     ph, &bh[0]);
                    mma_f16(oacc[2 * p + 1], pl, &bh[2]);
                    mma_f16(oacc[2 * p + 1], ph, &bh[2]);
                }
            }
        }
        __syncthreads();
    }

    // epilogue: normalize + bf16 split-store O
    float inv[2];
    inv[0] = 1.0f / l[0];
    inv[1] = 1.0f / l[1];
#pragma unroll
    for (int ni = 0; ni < 8; ni++) {
        int r = w * 16 + lq;
        int cu = ni * 4 + lr;
        size_t g0 = (size_t)(b * LL + qb + r) * 512 + h * 32 + cu;
        size_t g1 = (size_t)(b * LL + qb + r + 8) * 512 + h * 32 + cu;
        uint32_t lo, hi;
        hi = packsplit(oacc[ni][0] * inv[0], oacc[ni][1] * inv[0], lo);
        Oh_g[g0] = hi; Ol_g[g0] = lo;
        hi = packsplit(oacc[ni][2] * inv[1], oacc[ni][3] * inv[1], lo);
        Oh_g[g1] = hi; Ol_g[g1] = lo;
    }
}

// ---------------------------------------------------------------------------
extern "C" void kernel_launch(void* const* d_in, const int* in_sizes, int n_in,
                              void* d_out, int out_size)
{
    (void)in_sizes; (void)n_in; (void)out_size;
    const float* x    = (const float*)d_in[0];
    const float* Wq   = (const float*)d_in[1];
    const float* Wk   = (const float*)d_in[2];
    const float* Wv   = (const float*)d_in[3];
    const float* Wout = (const float*)d_in[4];
    float* out = (float*)d_out;

    __nv_bfloat16* g;
    cudaGetSymbolAddress((void**)&g, g_buf);

    __nv_bfloat16* xh    = g;
    __nv_bfloat16* xl    = g + M4;
    __nv_bfloat16* wqkvh = g + 8 * (size_t)M1;    // [3072][1024]
    __nv_bfloat16* wqkvl = g + 11 * (size_t)M1;
    __nv_bfloat16* woh   = g + 14 * (size_t)M1;
    __nv_bfloat16* wol   = g + 15 * (size_t)M1;
    __nv_bfloat16* qh    = g + 16 * (size_t)M1;   // fp16 bits
    __nv_bfloat16* ql    = g + 20 * (size_t)M1;   // fp16 bits
    __nv_bfloat16* kh    = g + 24 * (size_t)M1;   // fp16 bits (single)
    __nv_bfloat16* vth   = g + 32 * (size_t)M1;   // fp16 bits (single, transposed)
    __nv_bfloat16* oh    = g + 40 * (size_t)M1;   // bf16 hi
    __nv_bfloat16* ol    = g + 44 * (size_t)M1;   // bf16 lo

    // Prepasses
    split_kernel<<<M4 / 256, 256>>>(x, xh, xl, M4);
    WT4 wt;
    wt.s[0] = Wq;   wt.h[0] = wqkvh;                  wt.l[0] = wqkvl;
    wt.s[1] = Wk;   wt.h[1] = wqkvh + (size_t)M1;     wt.l[1] = wqkvl + (size_t)M1;
    wt.s[2] = Wv;   wt.h[2] = wqkvh + 2 * (size_t)M1; wt.l[2] = wqkvl + 2 * (size_t)M1;
    wt.s[3] = Wout; wt.h[3] = woh;                    wt.l[3] = wol;
    dim3 wtb(32, 8), wtg(32, 32, 4);
    wtrans4_kernel<<<wtg, wtb>>>(wt);

    const int gemm_smem = 20480 * 4;
    cudaFuncSetAttribute(gemm_bf16, cudaFuncAttributeMaxDynamicSharedMemorySize, gemm_smem);

    // Fused QKV GEMM: N=3072
    dim3 gqkv(3072 / 128, (BB * LL) / 128);
    gemm_bf16<<<gqkv, 256, gemm_smem>>>(xh, xl, wqkvh, wqkvl, nullptr, qh, ql, 3);

    const int attn_smem = (4608 * 2 + 4608 * 2) * 4;   // 73728 B
    cudaFuncSetAttribute(attn_f16, cudaFuncAttributeMaxDynamicSharedMemorySize, attn_smem);
    dim3 ga(LL / 128, HH, BB);
    attn_f16<<<ga, 256, attn_smem>>>(
        (const uint32_t*)qh, (const uint32_t*)ql,
        (const uint32_t*)kh, (const uint32_t*)vth,
        (uint32_t*)oh, (uint32_t*)ol);

    // Output projection: N=1024
    dim3 go(DD / 128, (BB * LL) / 128);
    gemm_bf16<<<go, 256, gemm_smem>>>(oh, ol, woh, wol, out, nullptr, nullptr, 0);
}

// round 14
// speedup vs baseline: 4.5307x; 1.2708x over previous
#include <cuda_runtime.h>
#include <cuda_bf16.h>
#include <cuda_fp16.h>
#include <math.h>
#include <stdint.h>

// Problem constants
#define BB 2
#define LL 2048
#define DD 1024
#define HH 16
#define DH 64
#define M1 1048576
#define M4 4194304

// One big scratch buffer (16-bit slots). Element offsets:
//  xh 0 (fp16 hi), xl 4M1 (fp16 lo), wqkvh 8M1 (3M1, fp16 single, transposed),
//  woh 14M1 (fp16 single, transposed), qh 16M1 (fp16 hi), ql 20M1 (fp16 lo),
//  kh 24M1 (fp16 single), vth 32M1 (fp16 single, per-head transposed),
//  oh 40M1 (fp16 hi), ol 44M1 (fp16 lo)
__device__ __nv_bfloat16 g_buf[48 * M1];

// ---------------------------------------------------------------------------
// Helpers
// ---------------------------------------------------------------------------
__device__ __forceinline__ uint32_t s2u(const void* p) {
    return (uint32_t)__cvta_generic_to_shared(p);
}

__device__ __forceinline__ void mma_f16(float* c, const uint32_t* a, const uint32_t* b) {
    asm volatile(
        "mma.sync.aligned.m16n8k16.row.col.f32.f16.f16.f32 "
        "{%0,%1,%2,%3}, {%4,%5,%6,%7}, {%8,%9}, {%0,%1,%2,%3};\n"
        : "+f"(c[0]), "+f"(c[1]), "+f"(c[2]), "+f"(c[3])
        : "r"(a[0]), "r"(a[1]), "r"(a[2]), "r"(a[3]), "r"(b[0]), "r"(b[1]));
}

__device__ __forceinline__ void ldsm4(uint32_t& r0, uint32_t& r1, uint32_t& r2, uint32_t& r3,
                                      uint32_t addr) {
    asm volatile("ldmatrix.sync.aligned.m8n8.x4.shared.b16 {%0,%1,%2,%3}, [%4];\n"
                 : "=r"(r0), "=r"(r1), "=r"(r2), "=r"(r3) : "r"(addr));
}

// fp16 split (pair) -> packed hi (return), lo (out)
__device__ __forceinline__ uint32_t packsplit_h(float x0, float x1, uint32_t& lo_out) {
    __half h0 = __float2half_rn(x0);
    __half h1 = __float2half_rn(x1);
    __half l0 = __float2half_rn(x0 - __half2float(h0));
    __half l1 = __float2half_rn(x1 - __half2float(h1));
    __half2 hp = __halves2half2(h0, h1);
    __half2 lp = __halves2half2(l0, l1);
    lo_out = *(uint32_t*)&lp;
    return *(uint32_t*)&hp;
}

__device__ __forceinline__ uint32_t packh(float x0, float x1) {
    __half2 hp = __floats2half2_rn(x0, x1);
    return *(uint32_t*)&hp;
}

__device__ __forceinline__ void cp_async16(uint32_t dst, const void* src) {
    asm volatile("cp.async.ca.shared.global [%0], [%1], 16;\n" :: "r"(dst), "l"(src));
}
__device__ __forceinline__ void cp_async16cg(uint32_t dst, const void* src) {
    asm volatile("cp.async.cg.shared.global [%0], [%1], 16;\n" :: "r"(dst), "l"(src));
}
__device__ __forceinline__ void cp_commit() {
    asm volatile("cp.async.commit_group;\n");
}
__device__ __forceinline__ void cp_wait0() {
    asm volatile("cp.async.wait_group 0;\n" ::: "memory");
}

// ---------------------------------------------------------------------------
// Prepass: elementwise fp32 -> fp16 hi/lo split (x)
// ---------------------------------------------------------------------------
__global__ __launch_bounds__(256) void split_kernel(
    const float* __restrict__ in, __half* __restrict__ hi,
    __half* __restrict__ lo, int n)
{
    int i = blockIdx.x * 256 + threadIdx.x;
    if (i >= n) return;
    float x = in[i];
    __half h = __float2half_rn(x);
    hi[i] = h;
    lo[i] = __float2half_rn(x - __half2float(h));
}

// ---------------------------------------------------------------------------
// Prepass: 4 weights [1024][1024] fp32 -> transposed fp16 single, one launch
// ---------------------------------------------------------------------------
struct WT4 {
    const float* s[4];
    __half* h[4];
};
__global__ __launch_bounds__(256) void wtrans4_kernel(WT4 wt)
{
    __shared__ float t[32][33];
    const int z = blockIdx.z;
    const float* W = wt.s[z];
    __half* th = wt.h[z];
    const int tx = threadIdx.x, ty = threadIdx.y;   // 32 x 8
    const int bx = blockIdx.x * 32, by = blockIdx.y * 32;
#pragma unroll
    for (int j = 0; j < 32; j += 8)
        t[ty + j][tx] = W[(size_t)(by + ty + j) * DD + bx + tx];
    __syncthreads();
#pragma unroll
    for (int j = 0; j < 32; j += 8) {
        size_t o = (size_t)(bx + ty + j) * DD + by + tx;
        th[o] = __float2half_rn(t[tx][ty + j]);
    }
}

// ---------------------------------------------------------------------------
// fp16 2-product GEMM: C[4096,N] = (Ah+Al) @ Wh^T.  A fp16 hi/lo, W fp16
// single (one-sided compensation). 128x128 block, K-stage 32, 8 warps
// (2m x 4n), warp tile 64x32, ldmatrix. Epilogue:
//   mode 0: fp32 C out.  mode 3: fused QKV routing
//     (cols 0-1023 -> Q fp16 hi/lo; 1024-2047 -> K fp16; 2048-3071 -> V fp16
//      per-head transposed).
// ---------------------------------------------------------------------------
#define GST 20
__global__ __launch_bounds__(256) void gemm_f16(
    const uint32_t* __restrict__ Ah4, const uint32_t* __restrict__ Al4,
    const uint32_t* __restrict__ Bh4,
    float* __restrict__ Cf, __half* __restrict__ Ch, __half* __restrict__ Cl,
    int mode)
{
    extern __shared__ uint32_t sg[];
    uint32_t* Ahs = sg;               // 2 stages x 128*GST
    uint32_t* Als = sg + 5120;
    uint32_t* Bhs = sg + 10240;       // total 15360 u32 = 61440 B

    const int tid = threadIdx.x;
    const int lane = tid & 31;
    const int wid = tid >> 5;
    const int warp_m = wid & 1;
    const int warp_n = wid >> 1;
    const int lq = lane >> 2;
    const int lr = lane & 3;
    const int l8 = lane & 7, lb3 = (lane >> 3) & 1, lb4 = lane >> 4;

    const int bm = blockIdx.y * 128;
    const int bn = blockIdx.x * 128;

    float acc[4][4][4];
#pragma unroll
    for (int mi = 0; mi < 4; mi++)
#pragma unroll
        for (int ni = 0; ni < 4; ni++)
#pragma unroll
            for (int q = 0; q < 4; q++) acc[mi][ni][q] = 0.0f;

    const uint32_t sAh = s2u(Ahs), sAl = s2u(Als), sBh = s2u(Bhs);

    const uint32_t a_off = (uint32_t)((warp_m * 64 + l8 + lb3 * 8) * GST + lb4 * 4);
    const uint32_t b_off = (uint32_t)((warp_n * 32 + l8 + lb4 * 8) * GST + lb3 * 4);

    auto load = [&](int buf, int k0u) {
#pragma unroll
        for (int j = 0; j < 2; j++) {
            int c = tid + j * 256;
            int r = c >> 2, q = (c & 3) * 4;
            uint32_t o = (uint32_t)(buf * 2560 + r * GST + q) * 4;
            size_t ao = (size_t)(bm + r) * 512 + k0u + q;
            size_t bo = (size_t)(bn + r) * 512 + k0u + q;
            cp_async16(sAh + o, Ah4 + ao);
            cp_async16(sAl + o, Al4 + ao);
            cp_async16(sBh + o, Bh4 + bo);
        }
        cp_commit();
    };

    load(0, 0);
    const int T = DD / 32;

    for (int t = 0; t < T; t++) {
        cp_wait0();
        __syncthreads();
        if (t + 1 < T) load((t + 1) & 1, (t + 1) * 16);

        const uint32_t stg = (uint32_t)(t & 1) * 2560 * 4;

#pragma unroll
        for (int kk = 0; kk < 2; kk++) {
            const uint32_t kb8 = kk * 8 * 4;
            uint32_t ah[4][4], al[4][4];
#pragma unroll
            for (int mi = 0; mi < 4; mi++) {
                uint32_t ad = stg + (a_off + mi * 16 * GST) * 4 + kb8;
                ldsm4(ah[mi][0], ah[mi][1], ah[mi][2], ah[mi][3], sAh + ad);
                ldsm4(al[mi][0], al[mi][1], al[mi][2], al[mi][3], sAl + ad);
            }
#pragma unroll
            for (int p = 0; p < 2; p++) {
                uint32_t bh[4];
                uint32_t bd = stg + (b_off + p * 16 * GST) * 4 + kb8;
                ldsm4(bh[0], bh[1], bh[2], bh[3], sBh + bd);
#pragma unroll
                for (int mi = 0; mi < 4; mi++) {
                    mma_f16(acc[mi][2 * p],     al[mi], &bh[0]);
                    mma_f16(acc[mi][2 * p],     ah[mi], &bh[0]);
                    mma_f16(acc[mi][2 * p + 1], al[mi], &bh[2]);
                    mma_f16(acc[mi][2 * p + 1], ah[mi], &bh[2]);
                }
            }
        }
        __syncthreads();
    }

    // ---- epilogue ----
    if (mode == 0) {
#pragma unroll
        for (int mi = 0; mi < 4; mi++)
#pragma unroll
            for (int ni = 0; ni < 4; ni++) {
                int r = bm + warp_m * 64 + mi * 16 + lq;
                int cc = bn + warp_n * 32 + ni * 8 + lr * 2;
                *(float2*)&Cf[(size_t)r * DD + cc] = make_float2(acc[mi][ni][0], acc[mi][ni][1]);
                *(float2*)&Cf[(size_t)(r + 8) * DD + cc] = make_float2(acc[mi][ni][2], acc[mi][ni][3]);
            }
    } else {
        // fused QKV routing (Ch = qh base; K/V at fixed offsets)
        uint32_t* QhU = (uint32_t*)Ch;
        uint32_t* QlU = (uint32_t*)Cl;
        uint32_t* KhU = (uint32_t*)(Ch + 8 * (size_t)M1);
        __half*   Vth = Ch + 16 * (size_t)M1;
#pragma unroll
        for (int mi = 0; mi < 4; mi++)
#pragma unroll
            for (int ni = 0; ni < 4; ni++) {
                int r = bm + warp_m * 64 + mi * 16 + lq;
                int cc = bn + warp_n * 32 + ni * 8 + lr * 2;
                int region = cc >> 10, lc = cc & 1023;
                if (region == 0) {
                    uint32_t lo, hi;
                    hi = packsplit_h(acc[mi][ni][0], acc[mi][ni][1], lo);
                    QhU[(size_t)r * 512 + (lc >> 1)] = hi;
                    QlU[(size_t)r * 512 + (lc >> 1)] = lo;
                    hi = packsplit_h(acc[mi][ni][2], acc[mi][ni][3], lo);
                    QhU[(size_t)(r + 8) * 512 + (lc >> 1)] = hi;
                    QlU[(size_t)(r + 8) * 512 + (lc >> 1)] = lo;
                } else if (region == 1) {
                    KhU[(size_t)r * 512 + (lc >> 1)] = packh(acc[mi][ni][0], acc[mi][ni][1]);
                    KhU[(size_t)(r + 8) * 512 + (lc >> 1)] = packh(acc[mi][ni][2], acc[mi][ni][3]);
                } else {
#pragma unroll
                    for (int q = 0; q < 4; q++) {
                        int rr = r + (q >> 1) * 8;
                        int ccl = lc + (q & 1);
                        int hh = ccl >> 6, e = ccl & 63, bI = rr >> 11, ltok = rr & 2047;
                        size_t dst = (((size_t)bI * HH + hh) * DH + e) * LL + ltok;
                        Vth[dst] = __float2half_rn(acc[mi][ni][q]);
                    }
                }
            }
    }
}

// ---------------------------------------------------------------------------
// fp16 2-product flash attention, causal (unchanged from round 13 except
// O epilogue emits fp16 hi/lo for the fp16 out-projection GEMM).
// ---------------------------------------------------------------------------
#define AS 36
__global__ __launch_bounds__(256) void attn_f16(
    const uint32_t* __restrict__ Qh_g, const uint32_t* __restrict__ Ql_g,
    const uint32_t* __restrict__ Kh_g, const uint32_t* __restrict__ Vh_g,
    uint32_t* __restrict__ Oh_g, uint32_t* __restrict__ Ol_g)
{
    extern __shared__ uint32_t sm[];
    uint32_t* Qh = sm;               // 128*AS = 4608
    uint32_t* Ql = Qh + 4608;
    uint32_t* KV = Ql + 4608;        // 2 stages x [Kh|Vh] x 2304

    const int tid = threadIdx.x;
    const int lane = tid & 31;
    const int w = tid >> 5;
    const int lq = lane >> 2;
    const int lr = lane & 3;
    const int l8 = lane & 7, lb3 = (lane >> 3) & 1, lb4 = lane >> 4;

    const int qt = (int)(gridDim.x - 1) - (int)blockIdx.x;
    const int h  = blockIdx.y;
    const int b  = blockIdx.z;
    const int qb = qt * 128;

    const uint32_t sQh = s2u(Qh), sQl = s2u(Ql), sKV = s2u(KV);

    const uint32_t q_off = (uint32_t)((w * 16 + l8 + lb3 * 8) * AS + lb4 * 4);
    const uint32_t kv_off = (uint32_t)((l8 + lb4 * 8) * AS + lb3 * 4);

#pragma unroll
    for (int j = 0; j < 4; j++) {
        int idx = tid + j * 256;
        int r = idx >> 3, cq = (idx & 7) * 4;
        size_t g = (size_t)(b * LL + qb + r) * 512 + h * 32 + cq;
        uint32_t o = (uint32_t)(r * AS + cq) * 4;
        cp_async16(sQh + o, Qh_g + g);
        cp_async16(sQl + o, Ql_g + g);
    }
    cp_commit();

    auto load_kv = [&](int buf, int kb) {
        uint32_t base = sKV + (uint32_t)buf * 4608 * 4;
#pragma unroll
        for (int j = 0; j < 2; j++) {
            int idx = tid + j * 256;
            int r = idx >> 3, cq = (idx & 7) * 4;
            uint32_t o = (uint32_t)(r * AS + cq) * 4;
            size_t gk = (size_t)(b * LL + kb + r) * 512 + h * 32 + cq;
            cp_async16cg(base + o, Kh_g + gk);
            size_t gv = ((size_t)(b * HH + h) * DH + r) * 1024 + (kb >> 1) + cq;
            cp_async16cg(base + 2304 * 4 + o, Vh_g + gv);
        }
        cp_commit();
    };

    load_kv(0, 0);

    float oacc[8][4];
    float m[2], l[2];
    m[0] = m[1] = -1e30f;
    l[0] = l[1] = 0.0f;
#pragma unroll
    for (int ni = 0; ni < 8; ni++)
#pragma unroll
        for (int q = 0; q < 4; q++) oacc[ni][q] = 0.0f;

    const int ntiles = 2 * qt + 2;
    for (int kt = 0; kt < ntiles; kt++) {
        const int kb = kt * 64;
        cp_wait0();
        __syncthreads();
        if (kt + 1 < ntiles) load_kv((kt + 1) & 1, (kt + 1) * 64);

        const bool active = (kb <= qb + w * 16 + 15);
        if (active) {
            const uint32_t kvb = sKV + (uint32_t)(kt & 1) * 4608 * 4;
            const uint32_t sKh = kvb, sVh = kvb + 2304 * 4;

            float sacc[8][4];
#pragma unroll
            for (int ni = 0; ni < 8; ni++)
#pragma unroll
                for (int q = 0; q < 4; q++) sacc[ni][q] = 0.0f;

#pragma unroll
            for (int kk = 0; kk < 4; kk++) {
                const uint32_t kb8 = kk * 8 * 4;
                uint32_t ah[4], al[4];
                uint32_t ad = q_off * 4 + kb8;
                ldsm4(ah[0], ah[1], ah[2], ah[3], sQh + ad);
                ldsm4(al[0], al[1], al[2], al[3], sQl + ad);
#pragma unroll
                for (int p = 0; p < 4; p++) {
                    uint32_t bh[4];
                    uint32_t bd = (kv_off + p * 16 * AS) * 4 + kb8;
                    ldsm4(bh[0], bh[1], bh[2], bh[3], sKh + bd);
                    mma_f16(sacc[2 * p],     al, &bh[0]);
                    mma_f16(sacc[2 * p],     ah, &bh[0]);
                    mma_f16(sacc[2 * p + 1], al, &bh[2]);
                    mma_f16(sacc[2 * p + 1], ah, &bh[2]);
                }
            }

            if (kb + 63 > qb + w * 16) {
#pragma unroll
                for (int ni = 0; ni < 8; ni++)
#pragma unroll
                    for (int q = 0; q < 4; q++) {
                        int row_g = qb + w * 16 + lq + (q >> 1) * 8;
                        int col_g = kb + ni * 8 + lr * 2 + (q & 1);
                        sacc[ni][q] = (col_g <= row_g) ? sacc[ni][q] * 0.125f : -1e30f;
                    }
            } else {
#pragma unroll
                for (int ni = 0; ni < 8; ni++)
#pragma unroll
                    for (int q = 0; q < 4; q++) sacc[ni][q] *= 0.125f;
            }

            float rmax[2] = {-1e30f, -1e30f};
#pragma unroll
            for (int ni = 0; ni < 8; ni++)
#pragma unroll
                for (int q = 0; q < 4; q++)
                    rmax[q >> 1] = fmaxf(rmax[q >> 1], sacc[ni][q]);
#pragma unroll
            for (int j = 0; j < 2; j++) {
                rmax[j] = fmaxf(rmax[j], __shfl_xor_sync(0xffffffffu, rmax[j], 1));
                rmax[j] = fmaxf(rmax[j], __shfl_xor_sync(0xffffffffu, rmax[j], 2));
            }

            float sc[2], rs[2];
#pragma unroll
            for (int j = 0; j < 2; j++) {
                float mn = fmaxf(m[j], rmax[j]);
                sc[j] = __expf(m[j] - mn);
                m[j] = mn;
                rs[j] = 0.0f;
            }
#pragma unroll
            for (int ni = 0; ni < 8; ni++)
#pragma unroll
                for (int q = 0; q < 4; q++) {
                    float p = __expf(sacc[ni][q] - m[q >> 1]);
                    sacc[ni][q] = p;
                    rs[q >> 1] += p;
                }
#pragma unroll
            for (int j = 0; j < 2; j++) {
                rs[j] += __shfl_xor_sync(0xffffffffu, rs[j], 1);
                rs[j] += __shfl_xor_sync(0xffffffffu, rs[j], 2);
                l[j] = l[j] * sc[j] + rs[j];
            }
#pragma unroll
            for (int ni = 0; ni < 8; ni++)
#pragma unroll
                for (int q = 0; q < 4; q++)
                    oacc[ni][q] *= sc[q >> 1];

#pragma unroll
            for (int kk = 0; kk < 4; kk++) {
                uint32_t ph[4], pl[4];
                ph[0] = packsplit_h(sacc[2 * kk][0],     sacc[2 * kk][1],     pl[0]);
                ph[1] = packsplit_h(sacc[2 * kk][2],     sacc[2 * kk][3],     pl[1]);
                ph[2] = packsplit_h(sacc[2 * kk + 1][0], sacc[2 * kk + 1][1], pl[2]);
                ph[3] = packsplit_h(sacc[2 * kk + 1][2], sacc[2 * kk + 1][3], pl[3]);
                const uint32_t kb8 = kk * 8 * 4;
#pragma unroll
                for (int p = 0; p < 4; p++) {
                    uint32_t bh[4];
                    uint32_t bd = (kv_off + p * 16 * AS) * 4 + kb8;
                    ldsm4(bh[0], bh[1], bh[2], bh[3], sVh + bd);
                    mma_f16(oacc[2 * p],     pl, &bh[0]);
                    mma_f16(oacc[2 * p],     ph, &bh[0]);
                    mma_f16(oacc[2 * p + 1], pl, &bh[2]);
                    mma_f16(oacc[2 * p + 1], ph, &bh[2]);
                }
            }
        }
        __syncthreads();
    }

    // epilogue: normalize + fp16 split-store O
    float inv[2];
    inv[0] = 1.0f / l[0];
    inv[1] = 1.0f / l[1];
#pragma unroll
    for (int ni = 0; ni < 8; ni++) {
        int r = w * 16 + lq;
        int cu = ni * 4 + lr;
        size_t g0 = (size_t)(b * LL + qb + r) * 512 + h * 32 + cu;
        size_t g1 = (size_t)(b * LL + qb + r + 8) * 512 + h * 32 + cu;
        uint32_t lo, hi;
        hi = packsplit_h(oacc[ni][0] * inv[0], oacc[ni][1] * inv[0], lo);
        Oh_g[g0] = hi; Ol_g[g0] = lo;
        hi = packsplit_h(oacc[ni][2] * inv[1], oacc[ni][3] * inv[1], lo);
        Oh_g[g1] = hi; Ol_g[g1] = lo;
    }
}

// ---------------------------------------------------------------------------
extern "C" void kernel_launch(void* const* d_in, const int* in_sizes, int n_in,
                              void* d_out, int out_size)
{
    (void)in_sizes; (void)n_in; (void)out_size;
    const float* x    = (const float*)d_in[0];
    const float* Wq   = (const float*)d_in[1];
    const float* Wk   = (const float*)d_in[2];
    const float* Wv   = (const float*)d_in[3];
    const float* Wout = (const float*)d_in[4];
    float* out = (float*)d_out;

    __nv_bfloat16* g;
    cudaGetSymbolAddress((void**)&g, g_buf);

    __half* xh    = (__half*)(g);
    __half* xl    = (__half*)(g + M4);
    __half* wqkvh = (__half*)(g + 8 * (size_t)M1);    // [3072][1024] fp16
    __half* woh   = (__half*)(g + 14 * (size_t)M1);
    __half* qh    = (__half*)(g + 16 * (size_t)M1);
    __half* ql    = (__half*)(g + 20 * (size_t)M1);
    __half* kh    = (__half*)(g + 24 * (size_t)M1);
    __half* vth   = (__half*)(g + 32 * (size_t)M1);
    __half* oh    = (__half*)(g + 40 * (size_t)M1);
    __half* ol    = (__half*)(g + 44 * (size_t)M1);

    // Prepasses
    split_kernel<<<M4 / 256, 256>>>(x, xh, xl, M4);
    WT4 wt;
    wt.s[0] = Wq;   wt.h[0] = wqkvh;
    wt.s[1] = Wk;   wt.h[1] = wqkvh + (size_t)M1;
    wt.s[2] = Wv;   wt.h[2] = wqkvh + 2 * (size_t)M1;
    wt.s[3] = Wout; wt.h[3] = woh;
    dim3 wtb(32, 8), wtg(32, 32, 4);
    wtrans4_kernel<<<wtg, wtb>>>(wt);

    const int gemm_smem = 15360 * 4;   // 61440 B
    cudaFuncSetAttribute(gemm_f16, cudaFuncAttributeMaxDynamicSharedMemorySize, gemm_smem);

    // Fused QKV GEMM: N=3072
    dim3 gqkv(3072 / 128, (BB * LL) / 128);
    gemm_f16<<<gqkv, 256, gemm_smem>>>((const uint32_t*)xh, (const uint32_t*)xl,
                                       (const uint32_t*)wqkvh, nullptr, qh, ql, 3);

    const int attn_smem = (4608 * 2 + 4608 * 2) * 4;   // 73728 B
    cudaFuncSetAttribute(attn_f16, cudaFuncAttributeMaxDynamicSharedMemorySize, attn_smem);
    dim3 ga(LL / 128, HH, BB);
    attn_f16<<<ga, 256, attn_smem>>>(
        (const uint32_t*)qh, (const uint32_t*)ql,
        (const uint32_t*)kh, (const uint32_t*)vth,
        (uint32_t*)oh, (uint32_t*)ol);

    // Output projection: N=1024
    dim3 go(DD / 128, (BB * LL) / 128);
    gemm_f16<<<go, 256, gemm_smem>>>((const uint32_t*)oh, (const uint32_t*)ol,
                                     (const uint32_t*)woh, out, nullptr, nullptr, 0);
}

// round 16
// speedup vs baseline: 5.1790x; 1.1431x over previous
#include <cuda_runtime.h>
#include <cuda_bf16.h>
#include <cuda_fp16.h>
#include <math.h>
#include <stdint.h>

// Problem constants
#define BB 2
#define LL 2048
#define DD 1024
#define HH 16
#define DH 64
#define M1 1048576
#define M4 4194304

// One big scratch buffer (16-bit slots). Element offsets:
//  xh 0 (fp16 hi), xl 4M1 (fp16 lo), wqkvh 8M1 (3M1, fp16 single, transposed),
//  woh 14M1 (fp16 single, transposed), qh 16M1 (fp16 hi), ql 20M1 (fp16 lo),
//  kh 24M1 (fp16 single), vth 32M1 (fp16 single, per-head transposed),
//  oh 40M1 (fp16 hi), ol 44M1 (fp16 lo)
__device__ __nv_bfloat16 g_buf[48 * M1];

// ---------------------------------------------------------------------------
// Helpers
// ---------------------------------------------------------------------------
__device__ __forceinline__ uint32_t s2u(const void* p) {
    return (uint32_t)__cvta_generic_to_shared(p);
}

__device__ __forceinline__ void mma_f16(float* c, const uint32_t* a, const uint32_t* b) {
    asm volatile(
        "mma.sync.aligned.m16n8k16.row.col.f32.f16.f16.f32 "
        "{%0,%1,%2,%3}, {%4,%5,%6,%7}, {%8,%9}, {%0,%1,%2,%3};\n"
        : "+f"(c[0]), "+f"(c[1]), "+f"(c[2]), "+f"(c[3])
        : "r"(a[0]), "r"(a[1]), "r"(a[2]), "r"(a[3]), "r"(b[0]), "r"(b[1]));
}

__device__ __forceinline__ void ldsm4(uint32_t& r0, uint32_t& r1, uint32_t& r2, uint32_t& r3,
                                      uint32_t addr) {
    asm volatile("ldmatrix.sync.aligned.m8n8.x4.shared.b16 {%0,%1,%2,%3}, [%4];\n"
                 : "=r"(r0), "=r"(r1), "=r"(r2), "=r"(r3) : "r"(addr));
}

// fp16 split (pair) -> packed hi (return), lo (out)
__device__ __forceinline__ uint32_t packsplit_h(float x0, float x1, uint32_t& lo_out) {
    __half h0 = __float2half_rn(x0);
    __half h1 = __float2half_rn(x1);
    __half l0 = __float2half_rn(x0 - __half2float(h0));
    __half l1 = __float2half_rn(x1 - __half2float(h1));
    __half2 hp = __halves2half2(h0, h1);
    __half2 lp = __halves2half2(l0, l1);
    lo_out = *(uint32_t*)&lp;
    return *(uint32_t*)&hp;
}

__device__ __forceinline__ uint32_t packh(float x0, float x1) {
    __half2 hp = __floats2half2_rn(x0, x1);
    return *(uint32_t*)&hp;
}

__device__ __forceinline__ void cp_async16(uint32_t dst, const void* src) {
    asm volatile("cp.async.ca.shared.global [%0], [%1], 16;\n" :: "r"(dst), "l"(src));
}
__device__ __forceinline__ void cp_async16cg(uint32_t dst, const void* src) {
    asm volatile("cp.async.cg.shared.global [%0], [%1], 16;\n" :: "r"(dst), "l"(src));
}
__device__ __forceinline__ void cp_commit() {
    asm volatile("cp.async.commit_group;\n");
}
__device__ __forceinline__ void cp_wait0() {
    asm volatile("cp.async.wait_group 0;\n" ::: "memory");
}

// ---------------------------------------------------------------------------
// Prepass: elementwise fp32 -> fp16 hi/lo split (x)
// ---------------------------------------------------------------------------
__global__ __launch_bounds__(256) void split_kernel(
    const float* __restrict__ in, __half* __restrict__ hi,
    __half* __restrict__ lo, int n)
{
    int i = blockIdx.x * 256 + threadIdx.x;
    if (i >= n) return;
    float x = in[i];
    __half h = __float2half_rn(x);
    hi[i] = h;
    lo[i] = __float2half_rn(x - __half2float(h));
}

// ---------------------------------------------------------------------------
// Prepass: 4 weights [1024][1024] fp32 -> transposed fp16 single, one launch
// ---------------------------------------------------------------------------
struct WT4 {
    const float* s[4];
    __half* h[4];
};
__global__ __launch_bounds__(256) void wtrans4_kernel(WT4 wt)
{
    __shared__ float t[32][33];
    const int z = blockIdx.z;
    const float* W = wt.s[z];
    __half* th = wt.h[z];
    const int tx = threadIdx.x, ty = threadIdx.y;   // 32 x 8
    const int bx = blockIdx.x * 32, by = blockIdx.y * 32;
#pragma unroll
    for (int j = 0; j < 32; j += 8)
        t[ty + j][tx] = W[(size_t)(by + ty + j) * DD + bx + tx];
    __syncthreads();
#pragma unroll
    for (int j = 0; j < 32; j += 8) {
        size_t o = (size_t)(bx + ty + j) * DD + by + tx;
        th[o] = __float2half_rn(t[tx][ty + j]);
    }
}

// ---------------------------------------------------------------------------
// fp16 GEMM: C[4096,N] = (Ah [+ Al]) @ Wh^T.  W fp16 single. use_al selects
// the A-side lo-correction product (out-proj keeps it; QKV drops it).
// 128x128 block, K-stage 32, 8 warps (2m x 4n), warp tile 64x32, ldmatrix.
// Epilogue: mode 0: fp32 C.  mode 3: fused QKV routing
//   (cols 0-1023 -> Q fp16 hi/lo; 1024-2047 -> K fp16; 2048-3071 -> V fp16
//    per-head transposed).
// ---------------------------------------------------------------------------
#define GST 20
__global__ __launch_bounds__(256) void gemm_f16(
    const uint32_t* __restrict__ Ah4, const uint32_t* __restrict__ Al4,
    const uint32_t* __restrict__ Bh4,
    float* __restrict__ Cf, __half* __restrict__ Ch, __half* __restrict__ Cl,
    int mode, int use_al)
{
    extern __shared__ uint32_t sg[];
    uint32_t* Ahs = sg;               // 2 stages x 128*GST
    uint32_t* Als = sg + 5120;
    uint32_t* Bhs = sg + 10240;       // total 15360 u32 = 61440 B

    const int tid = threadIdx.x;
    const int lane = tid & 31;
    const int wid = tid >> 5;
    const int warp_m = wid & 1;
    const int warp_n = wid >> 1;
    const int lq = lane >> 2;
    const int lr = lane & 3;
    const int l8 = lane & 7, lb3 = (lane >> 3) & 1, lb4 = lane >> 4;

    const int bm = blockIdx.y * 128;
    const int bn = blockIdx.x * 128;

    float acc[4][4][4];
#pragma unroll
    for (int mi = 0; mi < 4; mi++)
#pragma unroll
        for (int ni = 0; ni < 4; ni++)
#pragma unroll
            for (int q = 0; q < 4; q++) acc[mi][ni][q] = 0.0f;

    const uint32_t sAh = s2u(Ahs), sAl = s2u(Als), sBh = s2u(Bhs);

    const uint32_t a_off = (uint32_t)((warp_m * 64 + l8 + lb3 * 8) * GST + lb4 * 4);
    const uint32_t b_off = (uint32_t)((warp_n * 32 + l8 + lb4 * 8) * GST + lb3 * 4);

    auto load = [&](int buf, int k0u) {
#pragma unroll
        for (int j = 0; j < 2; j++) {
            int c = tid + j * 256;
            int r = c >> 2, q = (c & 3) * 4;
            uint32_t o = (uint32_t)(buf * 2560 + r * GST + q) * 4;
            size_t ao = (size_t)(bm + r) * 512 + k0u + q;
            size_t bo = (size_t)(bn + r) * 512 + k0u + q;
            cp_async16(sAh + o, Ah4 + ao);
            if (use_al) cp_async16(sAl + o, Al4 + ao);
            cp_async16(sBh + o, Bh4 + bo);
        }
        cp_commit();
    };

    load(0, 0);
    const int T = DD / 32;

    for (int t = 0; t < T; t++) {
        cp_wait0();
        __syncthreads();
        if (t + 1 < T) load((t + 1) & 1, (t + 1) * 16);

        const uint32_t stg = (uint32_t)(t & 1) * 2560 * 4;

#pragma unroll
        for (int kk = 0; kk < 2; kk++) {
            const uint32_t kb8 = kk * 8 * 4;
            uint32_t ah[4][4];
#pragma unroll
            for (int mi = 0; mi < 4; mi++) {
                uint32_t ad = stg + (a_off + mi * 16 * GST) * 4 + kb8;
                ldsm4(ah[mi][0], ah[mi][1], ah[mi][2], ah[mi][3], sAh + ad);
            }
            if (use_al) {
                uint32_t al[4][4];
#pragma unroll
                for (int mi = 0; mi < 4; mi++) {
                    uint32_t ad = stg + (a_off + mi * 16 * GST) * 4 + kb8;
                    ldsm4(al[mi][0], al[mi][1], al[mi][2], al[mi][3], sAl + ad);
                }
#pragma unroll
                for (int p = 0; p < 2; p++) {
                    uint32_t bh[4];
                    uint32_t bd = stg + (b_off + p * 16 * GST) * 4 + kb8;
                    ldsm4(bh[0], bh[1], bh[2], bh[3], sBh + bd);
#pragma unroll
                    for (int mi = 0; mi < 4; mi++) {
                        mma_f16(acc[mi][2 * p],     al[mi], &bh[0]);
                        mma_f16(acc[mi][2 * p],     ah[mi], &bh[0]);
                        mma_f16(acc[mi][2 * p + 1], al[mi], &bh[2]);
                        mma_f16(acc[mi][2 * p + 1], ah[mi], &bh[2]);
                    }
                }
            } else {
#pragma unroll
                for (int p = 0; p < 2; p++) {
                    uint32_t bh[4];
                    uint32_t bd = stg + (b_off + p * 16 * GST) * 4 + kb8;
                    ldsm4(bh[0], bh[1], bh[2], bh[3], sBh + bd);
#pragma unroll
                    for (int mi = 0; mi < 4; mi++) {
                        mma_f16(acc[mi][2 * p],     ah[mi], &bh[0]);
                        mma_f16(acc[mi][2 * p + 1], ah[mi], &bh[2]);
                    }
                }
            }
        }
        __syncthreads();
    }

    // ---- epilogue ----
    if (mode == 0) {
#pragma unroll
        for (int mi = 0; mi < 4; mi++)
#pragma unroll
            for (int ni = 0; ni < 4; ni++) {
                int r = bm + warp_m * 64 + mi * 16 + lq;
                int cc = bn + warp_n * 32 + ni * 8 + lr * 2;
                *(float2*)&Cf[(size_t)r * DD + cc] = make_float2(acc[mi][ni][0], acc[mi][ni][1]);
                *(float2*)&Cf[(size_t)(r + 8) * DD + cc] = make_float2(acc[mi][ni][2], acc[mi][ni][3]);
            }
    } else {
        // fused QKV routing (Ch = qh base; K/V at fixed offsets)
        uint32_t* QhU = (uint32_t*)Ch;
        uint32_t* QlU = (uint32_t*)Cl;
        uint32_t* KhU = (uint32_t*)(Ch + 8 * (size_t)M1);
        __half*   Vth = Ch + 16 * (size_t)M1;
#pragma unroll
        for (int mi = 0; mi < 4; mi++)
#pragma unroll
            for (int ni = 0; ni < 4; ni++) {
                int r = bm + warp_m * 64 + mi * 16 + lq;
                int cc = bn + warp_n * 32 + ni * 8 + lr * 2;
                int region = cc >> 10, lc = cc & 1023;
                if (region == 0) {
                    uint32_t lo, hi;
                    hi = packsplit_h(acc[mi][ni][0], acc[mi][ni][1], lo);
                    QhU[(size_t)r * 512 + (lc >> 1)] = hi;
                    QlU[(size_t)r * 512 + (lc >> 1)] = lo;
                    hi = packsplit_h(acc[mi][ni][2], acc[mi][ni][3], lo);
                    QhU[(size_t)(r + 8) * 512 + (lc >> 1)] = hi;
                    QlU[(size_t)(r + 8) * 512 + (lc >> 1)] = lo;
                } else if (region == 1) {
                    KhU[(size_t)r * 512 + (lc >> 1)] = packh(acc[mi][ni][0], acc[mi][ni][1]);
                    KhU[(size_t)(r + 8) * 512 + (lc >> 1)] = packh(acc[mi][ni][2], acc[mi][ni][3]);
                } else {
#pragma unroll
                    for (int q = 0; q < 4; q++) {
                        int rr = r + (q >> 1) * 8;
                        int ccl = lc + (q & 1);
                        int hh = ccl >> 6, e = ccl & 63, bI = rr >> 11, ltok = rr & 2047;
                        size_t dst = (((size_t)bI * HH + hh) * DH + e) * LL + ltok;
                        Vth[dst] = __float2half_rn(acc[mi][ni][q]);
                    }
                }
            }
    }
}

// ---------------------------------------------------------------------------
// fp16 2-product flash attention, causal (unchanged from round 14).
// ---------------------------------------------------------------------------
#define AS 36
__global__ __launch_bounds__(256) void attn_f16(
    const uint32_t* __restrict__ Qh_g, const uint32_t* __restrict__ Ql_g,
    const uint32_t* __restrict__ Kh_g, const uint32_t* __restrict__ Vh_g,
    uint32_t* __restrict__ Oh_g, uint32_t* __restrict__ Ol_g)
{
    extern __shared__ uint32_t sm[];
    uint32_t* Qh = sm;               // 128*AS = 4608
    uint32_t* Ql = Qh + 4608;
    uint32_t* KV = Ql + 4608;        // 2 stages x [Kh|Vh] x 2304

    const int tid = threadIdx.x;
    const int lane = tid & 31;
    const int w = tid >> 5;
    const int lq = lane >> 2;
    const int lr = lane & 3;
    const int l8 = lane & 7, lb3 = (lane >> 3) & 1, lb4 = lane >> 4;

    const int qt = (int)(gridDim.x - 1) - (int)blockIdx.x;
    const int h  = blockIdx.y;
    const int b  = blockIdx.z;
    const int qb = qt * 128;

    const uint32_t sQh = s2u(Qh), sQl = s2u(Ql), sKV = s2u(KV);

    const uint32_t q_off = (uint32_t)((w * 16 + l8 + lb3 * 8) * AS + lb4 * 4);
    const uint32_t kv_off = (uint32_t)((l8 + lb4 * 8) * AS + lb3 * 4);

#pragma unroll
    for (int j = 0; j < 4; j++) {
        int idx = tid + j * 256;
        int r = idx >> 3, cq = (idx & 7) * 4;
        size_t g = (size_t)(b * LL + qb + r) * 512 + h * 32 + cq;
        uint32_t o = (uint32_t)(r * AS + cq) * 4;
        cp_async16(sQh + o, Qh_g + g);
        cp_async16(sQl + o, Ql_g + g);
    }
    cp_commit();

    auto load_kv = [&](int buf, int kb) {
        uint32_t base = sKV + (uint32_t)buf * 4608 * 4;
#pragma unroll
        for (int j = 0; j < 2; j++) {
            int idx = tid + j * 256;
            int r = idx >> 3, cq = (idx & 7) * 4;
            uint32_t o = (uint32_t)(r * AS + cq) * 4;
            size_t gk = (size_t)(b * LL + kb + r) * 512 + h * 32 + cq;
            cp_async16cg(base + o, Kh_g + gk);
            size_t gv = ((size_t)(b * HH + h) * DH + r) * 1024 + (kb >> 1) + cq;
            cp_async16cg(base + 2304 * 4 + o, Vh_g + gv);
        }
        cp_commit();
    };

    load_kv(0, 0);

    float oacc[8][4];
    float m[2], l[2];
    m[0] = m[1] = -1e30f;
    l[0] = l[1] = 0.0f;
#pragma unroll
    for (int ni = 0; ni < 8; ni++)
#pragma unroll
        for (int q = 0; q < 4; q++) oacc[ni][q] = 0.0f;

    const int ntiles = 2 * qt + 2;
    for (int kt = 0; kt < ntiles; kt++) {
        const int kb = kt * 64;
        cp_wait0();
        __syncthreads();
        if (kt + 1 < ntiles) load_kv((kt + 1) & 1, (kt + 1) * 64);

        const bool active = (kb <= qb + w * 16 + 15);
        if (active) {
            const uint32_t kvb = sKV + (uint32_t)(kt & 1) * 4608 * 4;
            const uint32_t sKh = kvb, sVh = kvb + 2304 * 4;

            float sacc[8][4];
#pragma unroll
            for (int ni = 0; ni < 8; ni++)
#pragma unroll
                for (int q = 0; q < 4; q++) sacc[ni][q] = 0.0f;

#pragma unroll
            for (int kk = 0; kk < 4; kk++) {
                const uint32_t kb8 = kk * 8 * 4;
                uint32_t ah[4], al[4];
                uint32_t ad = q_off * 4 + kb8;
                ldsm4(ah[0], ah[1], ah[2], ah[3], sQh + ad);
                ldsm4(al[0], al[1], al[2], al[3], sQl + ad);
#pragma unroll
                for (int p = 0; p < 4; p++) {
                    uint32_t bh[4];
                    uint32_t bd = (kv_off + p * 16 * AS) * 4 + kb8;
                    ldsm4(bh[0], bh[1], bh[2], bh[3], sKh + bd);
                    mma_f16(sacc[2 * p],     al, &bh[0]);
                    mma_f16(sacc[2 * p],     ah, &bh[0]);
                    mma_f16(sacc[2 * p + 1], al, &bh[2]);
                    mma_f16(sacc[2 * p + 1], ah, &bh[2]);
                }
            }

            if (kb + 63 > qb + w * 16) {
#pragma unroll
                for (int ni = 0; ni < 8; ni++)
#pragma unroll
                    for (int q = 0; q < 4; q++) {
                        int row_g = qb + w * 16 + lq + (q >> 1) * 8;
                        int col_g = kb + ni * 8 + lr * 2 + (q & 1);
                        sacc[ni][q] = (col_g <= row_g) ? sacc[ni][q] * 0.125f : -1e30f;
                    }
            } else {
#pragma unroll
                for (int ni = 0; ni < 8; ni++)
#pragma unroll
                    for (int q = 0; q < 4; q++) sacc[ni][q] *= 0.125f;
            }

            float rmax[2] = {-1e30f, -1e30f};
#pragma unroll
            for (int ni = 0; ni < 8; ni++)
#pragma unroll
                for (int q = 0; q < 4; q++)
                    rmax[q >> 1] = fmaxf(rmax[q >> 1], sacc[ni][q]);
#pragma unroll
            for (int j = 0; j < 2; j++) {
                rmax[j] = fmaxf(rmax[j], __shfl_xor_sync(0xffffffffu, rmax[j], 1));
                rmax[j] = fmaxf(rmax[j], __shfl_xor_sync(0xffffffffu, rmax[j], 2));
            }

            float sc[2], rs[2];
#pragma unroll
            for (int j = 0; j < 2; j++) {
                float mn = fmaxf(m[j], rmax[j]);
                sc[j] = __expf(m[j] - mn);
                m[j] = mn;
                rs[j] = 0.0f;
            }
#pragma unroll
            for (int ni = 0; ni < 8; ni++)
#pragma unroll
                for (int q = 0; q < 4; q++) {
                    float p = __expf(sacc[ni][q] - m[q >> 1]);
                    sacc[ni][q] = p;
                    rs[q >> 1] += p;
                }
#pragma unroll
            for (int j = 0; j < 2; j++) {
                rs[j] += __shfl_xor_sync(0xffffffffu, rs[j], 1);
                rs[j] += __shfl_xor_sync(0xffffffffu, rs[j], 2);
                l[j] = l[j] * sc[j] + rs[j];
            }
#pragma unroll
            for (int ni = 0; ni < 8; ni++)
#pragma unroll
                for (int q = 0; q < 4; q++)
                    oacc[ni][q] *= sc[q >> 1];

#pragma unroll
            for (int kk = 0; kk < 4; kk++) {
                uint32_t ph[4], pl[4];
                ph[0] = packsplit_h(sacc[2 * kk][0],     sacc[2 * kk][1],     pl[0]);
                ph[1] = packsplit_h(sacc[2 * kk][2],     sacc[2 * kk][3],     pl[1]);
                ph[2] = packsplit_h(sacc[2 * kk + 1][0], sacc[2 * kk + 1][1], pl[2]);
                ph[3] = packsplit_h(sacc[2 * kk + 1][2], sacc[2 * kk + 1][3], pl[3]);
                const uint32_t kb8 = kk * 8 * 4;
#pragma unroll
                for (int p = 0; p < 4; p++) {
                    uint32_t bh[4];
                    uint32_t bd = (kv_off + p * 16 * AS) * 4 + kb8;
                    ldsm4(bh[0], bh[1], bh[2], bh[3], sVh + bd);
                    mma_f16(oacc[2 * p],     pl, &bh[0]);
                    mma_f16(oacc[2 * p],     ph, &bh[0]);
                    mma_f16(oacc[2 * p + 1], pl, &bh[2]);
                    mma_f16(oacc[2 * p + 1], ph, &bh[2]);
                }
            }
        }
        __syncthreads();
    }

    // epilogue: normalize + fp16 split-store O
    float inv[2];
    inv[0] = 1.0f / l[0];
    inv[1] = 1.0f / l[1];
#pragma unroll
    for (int ni = 0; ni < 8; ni++) {
        int r = w * 16 + lq;
        int cu = ni * 4 + lr;
        size_t g0 = (size_t)(b * LL + qb + r) * 512 + h * 32 + cu;
        size_t g1 = (size_t)(b * LL + qb + r + 8) * 512 + h * 32 + cu;
        uint32_t lo, hi;
        hi = packsplit_h(oacc[ni][0] * inv[0], oacc[ni][1] * inv[0], lo);
        Oh_g[g0] = hi; Ol_g[g0] = lo;
        hi = packsplit_h(oacc[ni][2] * inv[1], oacc[ni][3] * inv[1], lo);
        Oh_g[g1] = hi; Ol_g[g1] = lo;
    }
}

// ---------------------------------------------------------------------------
extern "C" void kernel_launch(void* const* d_in, const int* in_sizes, int n_in,
                              void* d_out, int out_size)
{
    (void)in_sizes; (void)n_in; (void)out_size;
    const float* x    = (const float*)d_in[0];
    const float* Wq   = (const float*)d_in[1];
    const float* Wk   = (const float*)d_in[2];
    const float* Wv   = (const float*)d_in[3];
    const float* Wout = (const float*)d_in[4];
    float* out = (float*)d_out;

    __nv_bfloat16* g;
    cudaGetSymbolAddress((void**)&g, g_buf);

    __half* xh    = (__half*)(g);
    __half* xl    = (__half*)(g + M4);
    __half* wqkvh = (__half*)(g + 8 * (size_t)M1);    // [3072][1024] fp16
    __half* woh   = (__half*)(g + 14 * (size_t)M1);
    __half* qh    = (__half*)(g + 16 * (size_t)M1);
    __half* ql    = (__half*)(g + 20 * (size_t)M1);
    __half* kh    = (__half*)(g + 24 * (size_t)M1);
    __half* vth   = (__half*)(g + 32 * (size_t)M1);
    __half* oh    = (__half*)(g + 40 * (size_t)M1);
    __half* ol    = (__half*)(g + 44 * (size_t)M1);

    // Prepasses
    split_kernel<<<M4 / 256, 256>>>(x, xh, xl, M4);
    WT4 wt;
    wt.s[0] = Wq;   wt.h[0] = wqkvh;
    wt.s[1] = Wk;   wt.h[1] = wqkvh + (size_t)M1;
    wt.s[2] = Wv;   wt.h[2] = wqkvh + 2 * (size_t)M1;
    wt.s[3] = Wout; wt.h[3] = woh;
    dim3 wtb(32, 8), wtg(32, 32, 4);
    wtrans4_kernel<<<wtg, wtb>>>(wt);

    const int gemm_smem = 15360 * 4;   // 61440 B
    cudaFuncSetAttribute(gemm_f16, cudaFuncAttributeMaxDynamicSharedMemorySize, gemm_smem);

    // Fused QKV GEMM: N=3072, single A-product (x_lo dropped)
    dim3 gqkv(3072 / 128, (BB * LL) / 128);
    gemm_f16<<<gqkv, 256, gemm_smem>>>((const uint32_t*)xh, (const uint32_t*)xl,
                                       (const uint32_t*)wqkvh, nullptr, qh, ql, 3, 0);

    const int attn_smem = (4608 * 2 + 4608 * 2) * 4;   // 73728 B
    cudaFuncSetAttribute(attn_f16, cudaFuncAttributeMaxDynamicSharedMemorySize, attn_smem);
    dim3 ga(LL / 128, HH, BB);
    attn_f16<<<ga, 256, attn_smem>>>(
        (const uint32_t*)qh, (const uint32_t*)ql,
        (const uint32_t*)kh, (const uint32_t*)vth,
        (uint32_t*)oh, (uint32_t*)ol);

    // Output projection: N=1024, keeps the o_lo correction product
    dim3 go(DD / 128, (BB * LL) / 128);
    gemm_f16<<<go, 256, gemm_smem>>>((const uint32_t*)oh, (const uint32_t*)ol,
                                     (const uint32_t*)woh, out, nullptr, nullptr, 0, 1);
}